// round 1
// baseline (speedup 1.0000x reference)
#include <cuda_runtime.h>
#include <cstddef>

#define T_STEPS 512
#define BATCH   64
#define HID     512
#define GATES   2048   // 4*HID, interleaved layout j' = h*4 + gate (f,i,g,o)
#define DIN     512

// ---------------- device scratch (static: no allocation APIs allowed) ----------
__device__ float g_Wx[GATES * DIN];        // 4 MB   Wx packed  [j'][k]
__device__ float g_Wh[GATES * HID];        // 4 MB   Wh packed  [j'][k]
__device__ float g_bias[GATES];            // 8 KB
__device__ float g_Gx[67108864];           // 256 MB Gx[(t*B+b)*2048 + j'] (x@Wx^T + b)
__device__ unsigned int g_bar;             // grid barrier counter

// ---------------- f32x2 helpers -----------------------------------------------
__device__ __forceinline__ unsigned long long pk2(float x, float y) {
    unsigned long long r;
    asm("mov.b64 %0, {%1, %2};" : "=l"(r) : "f"(x), "f"(y));
    return r;
}
__device__ __forceinline__ void fma2(unsigned long long& d, unsigned long long a,
                                     unsigned long long b) {
    asm("fma.rn.f32x2 %0, %1, %2, %0;" : "+l"(d) : "l"(a), "l"(b));
}
__device__ __forceinline__ void up2(unsigned long long v, float& x, float& y) {
    asm("mov.b64 {%0, %1}, %2;" : "=f"(x), "=f"(y) : "l"(v));
}
__device__ __forceinline__ float sigf(float x) {
    return 1.0f / (1.0f + __expf(-x));
}

// ---------------- repack weights into interleaved gate layout ------------------
// j' = h*4 + g so one block's 16 h-columns own 64 CONTIGUOUS gate columns,
// and the update phase reads f,i,g,o of one cell as a single float4.
__global__ void repack_kernel(const float* __restrict__ Wf, const float* __restrict__ Wi,
                              const float* __restrict__ Wg, const float* __restrict__ Wo,
                              const float* __restrict__ bf, const float* __restrict__ bi,
                              const float* __restrict__ bg, const float* __restrict__ bo) {
    int jp = blockIdx.x;            // 0..2047
    int h  = jp >> 2;
    int g  = jp & 3;
    const float* W = (g == 0) ? Wf : (g == 1) ? Wi : (g == 2) ? Wg : Wo;
    const float* B = (g == 0) ? bf : (g == 1) ? bi : (g == 2) ? bg : bo;
    const float* src = W + (size_t)h * (DIN + HID);
    for (int k = threadIdx.x; k < DIN; k += blockDim.x) {
        g_Wx[(size_t)jp * DIN + k] = src[k];
        g_Wh[(size_t)jp * HID + k] = src[DIN + k];
    }
    if (threadIdx.x == 0) {
        g_bias[jp] = B[h];
        if (jp == 0) g_bar = 0u;    // reset grid barrier each launch/replay
    }
}

// ---------------- input GEMM: Gx = X @ Wx^T + bias -----------------------------
// M = T*B = 32768, N = 2048, K = 512. 64x64 tile, 256 threads, 4x4 per thread,
// f32x2 packed FMAs (B pairs loaded directly as 64-bit from smem).
__global__ void __launch_bounds__(256) gemm_x_kernel(const float* __restrict__ X) {
    __shared__ __align__(16) float As[16][64];
    __shared__ __align__(16) float Bs[16][64];
    const int m0  = blockIdx.x * 64;
    const int n0  = blockIdx.y * 64;
    const int tid = threadIdx.x;
    const int tm4 = (tid >> 4) << 2;
    const int tn4 = (tid & 15) << 2;
    const int lr  = tid >> 2;        // 0..63
    const int lk  = (tid & 3) << 2;  // 0,4,8,12

    const float* Xp = X    + (size_t)(m0 + lr) * DIN + lk;
    const float* Wp = g_Wx + (size_t)(n0 + lr) * DIN + lk;

    unsigned long long acc[4][2];
#pragma unroll
    for (int i = 0; i < 4; i++) { acc[i][0] = pk2(0.f, 0.f); acc[i][1] = pk2(0.f, 0.f); }

    for (int kt = 0; kt < DIN; kt += 16) {
        float4 av = *(const float4*)(Xp + kt);
        float4 bv = *(const float4*)(Wp + kt);
        __syncthreads();
        As[lk + 0][lr] = av.x; As[lk + 1][lr] = av.y;
        As[lk + 2][lr] = av.z; As[lk + 3][lr] = av.w;
        Bs[lk + 0][lr] = bv.x; Bs[lk + 1][lr] = bv.y;
        Bs[lk + 2][lr] = bv.z; Bs[lk + 3][lr] = bv.w;
        __syncthreads();
#pragma unroll
        for (int k = 0; k < 16; k++) {
            float4 a = *(const float4*)&As[k][tm4];
            ulonglong2 b2 = *(const ulonglong2*)&Bs[k][tn4];  // (b0,b1),(b2,b3) packed
            unsigned long long t0;
            t0 = pk2(a.x, a.x); fma2(acc[0][0], b2.x, t0); fma2(acc[0][1], b2.y, t0);
            t0 = pk2(a.y, a.y); fma2(acc[1][0], b2.x, t0); fma2(acc[1][1], b2.y, t0);
            t0 = pk2(a.z, a.z); fma2(acc[2][0], b2.x, t0); fma2(acc[2][1], b2.y, t0);
            t0 = pk2(a.w, a.w); fma2(acc[3][0], b2.x, t0); fma2(acc[3][1], b2.y, t0);
        }
    }
    float4 bias = *(const float4*)&g_bias[n0 + tn4];
#pragma unroll
    for (int i = 0; i < 4; i++) {
        float c0, c1, c2, c3;
        up2(acc[i][0], c0, c1);
        up2(acc[i][1], c2, c3);
        float4 o;
        o.x = c0 + bias.x; o.y = c1 + bias.y; o.z = c2 + bias.z; o.w = c3 + bias.w;
        *(float4*)(g_Gx + (size_t)(m0 + tm4 + i) * GATES + n0 + tn4) = o;
    }
}

// ---------------- persistent recurrent kernel ----------------------------------
// Grid = 128 blocks (32 h-chunks x 4 batch-chunks), 128 threads, 1 block/SM.
// Each block keeps its Wh slice [512 K][64 gate-cols] in smem for all 512 steps.
// h broadcast lives in d_out itself: step t reads d_out[t-1], writes d_out[t].
// One device-wide spin barrier per step.
#define HS_STRIDE 520   // 16-row h tile, padded: conflict-free + 16B aligned
#define SMEM2_BYTES ((512 * 64 + 16 * HS_STRIDE + 16 * 64) * 4)

__global__ void __launch_bounds__(128, 1) lstm_kernel(float* __restrict__ out,
                                                      int write_tail) {
    extern __shared__ __align__(16) float sm[];
    float* Whs = sm;                        // [512][64]
    float* hs  = sm + 512 * 64;             // [16][HS_STRIDE]
    float* gsm = hs + 16 * HS_STRIDE;       // [16][64]

    const int bx  = blockIdx.x;
    const int h0  = (bx & 31) * 16;         // h columns [h0, h0+16)
    const int b0  = (bx >> 5) * 16;         // batch rows [b0, b0+16)
    const int c0g = h0 * 4;                 // first gate col (interleaved space)
    const int tid = threadIdx.x;

    // Load Wh slice once: Wh[j'][k] -> Whs[k][j], j local in [0,64)
    for (int idx = tid; idx < 64 * 128; idx += 128) {
        int j  = idx >> 7;
        int k4 = (idx & 127) << 2;
        float4 w = *(const float4*)(g_Wh + (size_t)(c0g + j) * HID + k4);
        Whs[(k4 + 0) * 64 + j] = w.x;
        Whs[(k4 + 1) * 64 + j] = w.y;
        Whs[(k4 + 2) * 64 + j] = w.z;
        Whs[(k4 + 3) * 64 + j] = w.w;
    }

    const int rb   = tid >> 3;              // local batch row 0..15
    const int cg   = tid & 7;
    const int colA = cg * 4;                // bank-conflict-free split columns
    const int colB = 32 + cg * 4;
    const int ub0  = tid >> 4;              // update cell 0: (ub0, uh0)
    const int uh0  = tid & 15;              // update cell 1: (ub0+8, uh0)

    float cA = 0.f, cB = 0.f;
    __syncthreads();

    for (int t = 0; t < T_STEPS; t++) {
        // ---- load h(t-1) tile (L2-coherent: other SMs wrote it this launch) ----
        if (t == 0) {
            for (int idx = tid; idx < 16 * HS_STRIDE; idx += 128) hs[idx] = 0.f;
        } else {
            const float* hsrc = out + ((size_t)(t - 1) * BATCH + b0) * HID;
#pragma unroll 4
            for (int idx = tid; idx < 2048; idx += 128) {
                int r  = idx >> 7;
                int k4 = (idx & 127) << 2;
                float4 v = __ldcg((const float4*)(hsrc + (size_t)r * HID + k4));
                *(float4*)&hs[r * HS_STRIDE + k4] = v;
            }
        }
        __syncthreads();

        // ---- gates = Gx[t] + h @ Wh^T for this block's 16x64 tile --------------
        const float* gx = g_Gx + ((size_t)t * BATCH + b0 + rb) * GATES + c0g;
        float4 iA = *(const float4*)(gx + colA);
        float4 iB = *(const float4*)(gx + colB);
        unsigned long long aA0 = pk2(iA.x, iA.y), aA1 = pk2(iA.z, iA.w);
        unsigned long long aB0 = pk2(iB.x, iB.y), aB1 = pk2(iB.z, iB.w);

        const float* hrow = hs + rb * HS_STRIDE;
#pragma unroll 4
        for (int k = 0; k < HID; k += 4) {
            float4 h4 = *(const float4*)(hrow + k);
            const float* wp = Whs + (size_t)k * 64;
            {
                unsigned long long hd = pk2(h4.x, h4.x);
                ulonglong2 wa = *(const ulonglong2*)(wp + colA);
                ulonglong2 wb = *(const ulonglong2*)(wp + colB);
                fma2(aA0, wa.x, hd); fma2(aA1, wa.y, hd);
                fma2(aB0, wb.x, hd); fma2(aB1, wb.y, hd);
            }
            {
                unsigned long long hd = pk2(h4.y, h4.y);
                ulonglong2 wa = *(const ulonglong2*)(wp + 64 + colA);
                ulonglong2 wb = *(const ulonglong2*)(wp + 64 + colB);
                fma2(aA0, wa.x, hd); fma2(aA1, wa.y, hd);
                fma2(aB0, wb.x, hd); fma2(aB1, wb.y, hd);
            }
            {
                unsigned long long hd = pk2(h4.z, h4.z);
                ulonglong2 wa = *(const ulonglong2*)(wp + 128 + colA);
                ulonglong2 wb = *(const ulonglong2*)(wp + 128 + colB);
                fma2(aA0, wa.x, hd); fma2(aA1, wa.y, hd);
                fma2(aB0, wb.x, hd); fma2(aB1, wb.y, hd);
            }
            {
                unsigned long long hd = pk2(h4.w, h4.w);
                ulonglong2 wa = *(const ulonglong2*)(wp + 192 + colA);
                ulonglong2 wb = *(const ulonglong2*)(wp + 192 + colB);
                fma2(aA0, wa.x, hd); fma2(aA1, wa.y, hd);
                fma2(aB0, wb.x, hd); fma2(aB1, wb.y, hd);
            }
        }
        {
            float q0, q1, q2, q3;
            up2(aA0, q0, q1); up2(aA1, q2, q3);
            *(float4*)&gsm[rb * 64 + colA] = make_float4(q0, q1, q2, q3);
            up2(aB0, q0, q1); up2(aB1, q2, q3);
            *(float4*)&gsm[rb * 64 + colB] = make_float4(q0, q1, q2, q3);
        }
        __syncthreads();

        // ---- elementwise LSTM update: 2 cells per thread -----------------------
        float hA, hB;
        {
            float4 gv = *(const float4*)&gsm[ub0 * 64 + uh0 * 4];   // f,i,g,o
            float f = sigf(gv.x), ii = sigf(gv.y), gg = tanhf(gv.z), o = sigf(gv.w);
            cA = f * cA + ii * gg;
            hA = o * tanhf(cA);
            out[((size_t)t * BATCH + b0 + ub0) * HID + h0 + uh0] = hA;
        }
        {
            float4 gv = *(const float4*)&gsm[(ub0 + 8) * 64 + uh0 * 4];
            float f = sigf(gv.x), ii = sigf(gv.y), gg = tanhf(gv.z), o = sigf(gv.w);
            cB = f * cB + ii * gg;
            hB = o * tanhf(cB);
            out[((size_t)t * BATCH + b0 + ub0 + 8) * HID + h0 + uh0] = hB;
        }
        if (write_tail && t == T_STEPS - 1) {
            size_t base = (size_t)T_STEPS * BATCH * HID;
            out[base + (size_t)(b0 + ub0) * HID + h0 + uh0]     = hA;
            out[base + (size_t)(b0 + ub0 + 8) * HID + h0 + uh0] = hB;
            base += (size_t)BATCH * HID;
            out[base + (size_t)(b0 + ub0) * HID + h0 + uh0]     = cA;
            out[base + (size_t)(b0 + ub0 + 8) * HID + h0 + uh0] = cB;
        }

        // ---- device-wide barrier ----------------------------------------------
        __threadfence();
        __syncthreads();
        if (tid == 0) {
            atomicAdd(&g_bar, 1u);
            unsigned int target = (unsigned int)(t + 1) * gridDim.x;
            unsigned int v;
            do {
                asm volatile("ld.acquire.gpu.u32 %0, [%1];" : "=r"(v) : "l"(&g_bar));
            } while (v < target);
        }
        __syncthreads();
    }
}

// ---------------- launch --------------------------------------------------------
extern "C" void kernel_launch(void* const* d_in, const int* in_sizes, int n_in,
                              void* d_out, int out_size) {
    const float* x  = (const float*)d_in[0];
    const float* Wf = (const float*)d_in[1];
    const float* bf = (const float*)d_in[2];
    const float* Wi = (const float*)d_in[3];
    const float* bi = (const float*)d_in[4];
    const float* Wg = (const float*)d_in[5];
    const float* bg = (const float*)d_in[6];
    const float* Wo = (const float*)d_in[7];
    const float* bo = (const float*)d_in[8];
    float* out = (float*)d_out;

    const long long tbh = (long long)T_STEPS * BATCH * HID;
    int write_tail = ((long long)out_size >= tbh + 2LL * BATCH * HID) ? 1 : 0;

    cudaFuncSetAttribute(lstm_kernel, cudaFuncAttributeMaxDynamicSharedMemorySize,
                         SMEM2_BYTES);

    repack_kernel<<<GATES, 128>>>(Wf, Wi, Wg, Wo, bf, bi, bg, bo);
    dim3 g1(T_STEPS * BATCH / 64, GATES / 64);
    gemm_x_kernel<<<g1, 256>>>(x);
    lstm_kernel<<<128, 128, SMEM2_BYTES>>>(out, write_tail);
}

// round 2
// speedup vs baseline: 1.5320x; 1.5320x over previous
#include <cuda_runtime.h>
#include <cstddef>

#define T_STEPS 512
#define BATCH   64
#define HID     512
#define GATES   2048   // 4*HID, interleaved j' = h*4 + gate (f,i,g,o)
#define DIN     512
#define NBLK    128

#define WS  68    // Whs row stride (floats): 16B-aligned rows, conflict-free
#define HSS 516   // hs row stride: 516 % 32 == 4 -> 2-phase h loads
#define GS  68    // gsm/gpr row stride

// ---------------- device scratch --------------------------------------------
__device__ float g_Gx[67108864];   // 256 MB  Gx[(t*B+b)*2048 + j']  (x@Wx^T + b)
__device__ unsigned int g_bar;

// ---------------- f32x2 helpers ---------------------------------------------
__device__ __forceinline__ unsigned long long pk2(float x, float y) {
    unsigned long long r;
    asm("mov.b64 %0, {%1, %2};" : "=l"(r) : "f"(x), "f"(y));
    return r;
}
__device__ __forceinline__ void fma2(unsigned long long& d, unsigned long long a,
                                     unsigned long long b) {
    asm("fma.rn.f32x2 %0, %1, %2, %0;" : "+l"(d) : "l"(a), "l"(b));
}
__device__ __forceinline__ void up2(unsigned long long v, float& x, float& y) {
    asm("mov.b64 {%0, %1}, %2;" : "=f"(x), "=f"(y) : "l"(v));
}
__device__ __forceinline__ float sigf(float x) {
    return __fdividef(1.0f, 1.0f + __expf(-x));
}
__device__ __forceinline__ float tanhfast(float x) {
    return fmaf(2.0f, sigf(2.0f * x), -1.0f);
}

// ---------------- input GEMM: Gx = X @ Wx^T + bias ---------------------------
// M=T*B=32768, N=2048, K=512. 64x64 tile, 256 threads, 4x4/thread, f32x2 FMAs.
// Reads the original W arrays directly (col j' = h*4+g decode). Resets g_bar.
__global__ void __launch_bounds__(256) gemm_x_kernel(
    const float* __restrict__ X,
    const float* __restrict__ Wf, const float* __restrict__ Wi,
    const float* __restrict__ Wg, const float* __restrict__ Wo,
    const float* __restrict__ bf, const float* __restrict__ bi,
    const float* __restrict__ bg, const float* __restrict__ bo) {
    __shared__ __align__(16) float As[16][64];
    __shared__ __align__(16) float Bs[16][64];
    if (blockIdx.x == 0 && blockIdx.y == 0 && threadIdx.x == 0) g_bar = 0u;

    const int m0  = blockIdx.x * 64;
    const int n0  = blockIdx.y * 64;
    const int tid = threadIdx.x;
    const int tm4 = (tid >> 4) << 2;
    const int tn4 = (tid & 15) << 2;
    const int lr  = tid >> 2;        // 0..63
    const int lk  = (tid & 3) << 2;  // 0,4,8,12

    const float* Xp = X + (size_t)(m0 + lr) * DIN + lk;
    const int jp = n0 + lr;
    const int gg = jp & 3;
    const int hh = jp >> 2;
    const float* Wsel = (gg == 0) ? Wf : (gg == 1) ? Wi : (gg == 2) ? Wg : Wo;
    const float* Wp = Wsel + (size_t)hh * (DIN + HID) + lk;   // Wx part: cols [0,512)

    unsigned long long acc[4][2];
#pragma unroll
    for (int i = 0; i < 4; i++) { acc[i][0] = pk2(0.f, 0.f); acc[i][1] = pk2(0.f, 0.f); }

    for (int kt = 0; kt < DIN; kt += 16) {
        float4 av = *(const float4*)(Xp + kt);
        float4 bv = *(const float4*)(Wp + kt);
        __syncthreads();
        As[lk + 0][lr] = av.x; As[lk + 1][lr] = av.y;
        As[lk + 2][lr] = av.z; As[lk + 3][lr] = av.w;
        Bs[lk + 0][lr] = bv.x; Bs[lk + 1][lr] = bv.y;
        Bs[lk + 2][lr] = bv.z; Bs[lk + 3][lr] = bv.w;
        __syncthreads();
#pragma unroll
        for (int k = 0; k < 16; k++) {
            float4 a = *(const float4*)&As[k][tm4];
            ulonglong2 b2 = *(const ulonglong2*)&Bs[k][tn4];
            unsigned long long t0;
            t0 = pk2(a.x, a.x); fma2(acc[0][0], b2.x, t0); fma2(acc[0][1], b2.y, t0);
            t0 = pk2(a.y, a.y); fma2(acc[1][0], b2.x, t0); fma2(acc[1][1], b2.y, t0);
            t0 = pk2(a.z, a.z); fma2(acc[2][0], b2.x, t0); fma2(acc[2][1], b2.y, t0);
            t0 = pk2(a.w, a.w); fma2(acc[3][0], b2.x, t0); fma2(acc[3][1], b2.y, t0);
        }
    }
    const int hb = (n0 + tn4) >> 2;            // cols n0+tn4+i have gate i of cell hb
    float4 bias = make_float4(bf[hb], bi[hb], bg[hb], bo[hb]);
#pragma unroll
    for (int i = 0; i < 4; i++) {
        float c0, c1, c2, c3;
        up2(acc[i][0], c0, c1);
        up2(acc[i][1], c2, c3);
        float4 o;
        o.x = c0 + bias.x; o.y = c1 + bias.y; o.z = c2 + bias.z; o.w = c3 + bias.w;
        *(float4*)(g_Gx + (size_t)(m0 + tm4 + i) * GATES + n0 + tn4) = o;
    }
}

// ---------------- persistent recurrent kernel --------------------------------
// 128 blocks (32 h-chunks x 4 batch-chunks), 256 threads (2 warps/SMSP).
// Block tile: 16 batch rows x 64 gate cols. Wh slice resident in smem.
// Warp = (cgrp<<1)|kh: 16 cols, K half. Lane = kq(1) x ch(1) x rp(3):
// each lane: rows {rp, rp+8} x 8 cols x 128 K  -> 8 f32x2 accumulators.
#define SMEM2_BYTES ((512 * WS + 16 * HSS + 2 * 16 * GS) * 4)

__global__ void __launch_bounds__(256, 1) lstm_kernel(
    float* __restrict__ out, int write_tail,
    const float* __restrict__ Wf, const float* __restrict__ Wi,
    const float* __restrict__ Wg, const float* __restrict__ Wo) {
    extern __shared__ __align__(16) float sm[];
    float* Whs = sm;                    // [512][WS]
    float* hs  = Whs + 512 * WS;        // [16][HSS]
    float* gsm = hs + 16 * HSS;         // [16][GS]  final gate preacts
    float* gpr = gsm + 16 * GS;         // [16][GS]  kh=1 partials

    const int tid = threadIdx.x;
    const int bx  = blockIdx.x;
    const int h0  = (bx & 31) * 16;
    const int b0  = (bx >> 5) * 16;
    const int c0g = h0 * 4;

    // ---- prologue: load Wh slice [512 K][64 cols] into smem, j-major STS ----
    {
        const int j     = tid & 63;
        const int kbase = (tid >> 6) * 128;
        const int jp = c0g + j;
        const int g  = jp & 3;
        const int hh = jp >> 2;
        const float* Wsel = (g == 0) ? Wf : (g == 1) ? Wi : (g == 2) ? Wg : Wo;
        const float* src = Wsel + (size_t)hh * (DIN + HID) + DIN + kbase;
#pragma unroll 4
        for (int k4 = 0; k4 < 128; k4 += 4) {
            float4 w = *(const float4*)(src + k4);
            int kk = kbase + k4;
            Whs[(kk + 0) * WS + j] = w.x;
            Whs[(kk + 1) * WS + j] = w.y;
            Whs[(kk + 2) * WS + j] = w.z;
            Whs[(kk + 3) * WS + j] = w.w;
        }
    }

    const int w    = tid >> 5;
    const int lane = tid & 31;
    const int kh   = w & 1;                   // K half (256)
    const int cgrp = w >> 1;                  // col group of 16
    const int rp   = lane & 7;                // rows rp, rp+8
    const int ch   = (lane >> 3) & 1;         // col sub-half (8 cols)
    const int kq   = lane >> 4;               // K quarter within half (128)
    const int colbase = cgrp * 16 + ch * 8;
    const int kstart  = kh * 256 + kq * 128;
    const bool writer = (kq == 0);

    const int urow = tid >> 4;                // update cell (urow, ucol)
    const int ucol = tid & 15;

    float c_state = 0.f;
    float h_last  = 0.f;

    // Gx prefetch registers (used by kh==0 && kq==0 lanes)
    float4 gxA0, gxA1, gxB0, gxB1;
    const float* gxp0 = g_Gx + ((size_t)b0 + rp) * GATES + c0g + colbase;
    if (kh == 0 && writer) {
        gxA0 = __ldcg((const float4*)(gxp0));
        gxA1 = __ldcg((const float4*)(gxp0 + 4));
        gxB0 = __ldcg((const float4*)(gxp0 + 8 * GATES));
        gxB1 = __ldcg((const float4*)(gxp0 + 8 * GATES + 4));
    }
    __syncthreads();

    for (int t = 0; t < T_STEPS; t++) {
        unsigned long long aA0 = pk2(0.f, 0.f), aA1 = aA0, aA2 = aA0, aA3 = aA0;
        unsigned long long aB0 = aA0, aB1 = aA0, aB2 = aA0, aB3 = aA0;

        if (t > 0) {
            // ---- load h(t-1) tile from gmem (L2) --------------------------------
            const float* hsrc = out + ((size_t)(t - 1) * BATCH + b0) * HID;
#pragma unroll
            for (int i = 0; i < 8; i++) {
                int idx = tid + i * 256;                 // 2048 float4
                int r   = idx >> 7;
                int k4  = (idx & 127) << 2;
                float4 v = __ldcg((const float4*)(hsrc + (size_t)r * HID + k4));
                *(float4*)&hs[r * HSS + k4] = v;
            }
            __syncthreads();

            // ---- partial GEMM: rows {rp, rp+8}, 8 cols, 128 K -------------------
            const float* hr0 = hs + rp * HSS + kstart;
            const float* hr1 = hs + (rp + 8) * HSS + kstart;
            const float* wk  = Whs + (size_t)kstart * WS + colbase;
#pragma unroll 2
            for (int kg = 0; kg < 128; kg += 4) {
                float4 hx = *(const float4*)(hr0 + kg);
                float4 hy = *(const float4*)(hr1 + kg);
                const float* wp = wk + (size_t)kg * WS;
                {
                    ulonglong2 w0 = *(const ulonglong2*)(wp);
                    ulonglong2 w1 = *(const ulonglong2*)(wp + 4);
                    unsigned long long d0 = pk2(hx.x, hx.x), d1 = pk2(hy.x, hy.x);
                    fma2(aA0, w0.x, d0); fma2(aA1, w0.y, d0);
                    fma2(aA2, w1.x, d0); fma2(aA3, w1.y, d0);
                    fma2(aB0, w0.x, d1); fma2(aB1, w0.y, d1);
                    fma2(aB2, w1.x, d1); fma2(aB3, w1.y, d1);
                }
                {
                    ulonglong2 w0 = *(const ulonglong2*)(wp + WS);
                    ulonglong2 w1 = *(const ulonglong2*)(wp + WS + 4);
                    unsigned long long d0 = pk2(hx.y, hx.y), d1 = pk2(hy.y, hy.y);
                    fma2(aA0, w0.x, d0); fma2(aA1, w0.y, d0);
                    fma2(aA2, w1.x, d0); fma2(aA3, w1.y, d0);
                    fma2(aB0, w0.x, d1); fma2(aB1, w0.y, d1);
                    fma2(aB2, w1.x, d1); fma2(aB3, w1.y, d1);
                }
                {
                    ulonglong2 w0 = *(const ulonglong2*)(wp + 2 * WS);
                    ulonglong2 w1 = *(const ulonglong2*)(wp + 2 * WS + 4);
                    unsigned long long d0 = pk2(hx.z, hx.z), d1 = pk2(hy.z, hy.z);
                    fma2(aA0, w0.x, d0); fma2(aA1, w0.y, d0);
                    fma2(aA2, w1.x, d0); fma2(aA3, w1.y, d0);
                    fma2(aB0, w0.x, d1); fma2(aB1, w0.y, d1);
                    fma2(aB2, w1.x, d1); fma2(aB3, w1.y, d1);
                }
                {
                    ulonglong2 w0 = *(const ulonglong2*)(wp + 3 * WS);
                    ulonglong2 w1 = *(const ulonglong2*)(wp + 3 * WS + 4);
                    unsigned long long d0 = pk2(hx.w, hx.w), d1 = pk2(hy.w, hy.w);
                    fma2(aA0, w0.x, d0); fma2(aA1, w0.y, d0);
                    fma2(aA2, w1.x, d0); fma2(aA3, w1.y, d0);
                    fma2(aB0, w0.x, d1); fma2(aB1, w0.y, d1);
                    fma2(aB2, w1.x, d1); fma2(aB3, w1.y, d1);
                }
            }
        }

        // ---- reduce K quarters (shuffle across kq bit = lane bit 4) -------------
        float r[16];
        up2(aA0, r[0], r[1]);  up2(aA1, r[2], r[3]);
        up2(aA2, r[4], r[5]);  up2(aA3, r[6], r[7]);
        up2(aB0, r[8], r[9]);  up2(aB1, r[10], r[11]);
        up2(aB2, r[12], r[13]); up2(aB3, r[14], r[15]);
#pragma unroll
        for (int i = 0; i < 16; i++)
            r[i] += __shfl_xor_sync(0xffffffffu, r[i], 16);

        // ---- reduce K halves through smem, add Gx -------------------------------
        if (kh == 1 && writer) {
            *(float4*)&gpr[rp * GS + colbase]           = make_float4(r[0], r[1], r[2], r[3]);
            *(float4*)&gpr[rp * GS + colbase + 4]       = make_float4(r[4], r[5], r[6], r[7]);
            *(float4*)&gpr[(rp + 8) * GS + colbase]     = make_float4(r[8], r[9], r[10], r[11]);
            *(float4*)&gpr[(rp + 8) * GS + colbase + 4] = make_float4(r[12], r[13], r[14], r[15]);
        }
        __syncthreads();
        if (kh == 0 && writer) {
            float4 p0 = *(const float4*)&gpr[rp * GS + colbase];
            float4 p1 = *(const float4*)&gpr[rp * GS + colbase + 4];
            float4 p2 = *(const float4*)&gpr[(rp + 8) * GS + colbase];
            float4 p3 = *(const float4*)&gpr[(rp + 8) * GS + colbase + 4];
            *(float4*)&gsm[rp * GS + colbase] =
                make_float4(r[0] + p0.x + gxA0.x, r[1] + p0.y + gxA0.y,
                            r[2] + p0.z + gxA0.z, r[3] + p0.w + gxA0.w);
            *(float4*)&gsm[rp * GS + colbase + 4] =
                make_float4(r[4] + p1.x + gxA1.x, r[5] + p1.y + gxA1.y,
                            r[6] + p1.z + gxA1.z, r[7] + p1.w + gxA1.w);
            *(float4*)&gsm[(rp + 8) * GS + colbase] =
                make_float4(r[8] + p2.x + gxB0.x, r[9] + p2.y + gxB0.y,
                            r[10] + p2.z + gxB0.z, r[11] + p2.w + gxB0.w);
            *(float4*)&gsm[(rp + 8) * GS + colbase + 4] =
                make_float4(r[12] + p3.x + gxB1.x, r[13] + p3.y + gxB1.y,
                            r[14] + p3.z + gxB1.z, r[15] + p3.w + gxB1.w);
        }

        // ---- prefetch Gx for t+1 (off the critical path, before barrier) --------
        if (kh == 0 && writer && t + 1 < T_STEPS) {
            const float* gxp = gxp0 + (size_t)(t + 1) * BATCH * GATES;
            gxA0 = __ldcg((const float4*)(gxp));
            gxA1 = __ldcg((const float4*)(gxp + 4));
            gxB0 = __ldcg((const float4*)(gxp + 8 * GATES));
            gxB1 = __ldcg((const float4*)(gxp + 8 * GATES + 4));
        }
        __syncthreads();

        // ---- elementwise LSTM update: 1 cell per thread -------------------------
        {
            float4 gv = *(const float4*)&gsm[urow * GS + ucol * 4];  // f,i,g,o
            float f  = sigf(gv.x);
            float ii = sigf(gv.y);
            float gg = tanhfast(gv.z);
            float o  = sigf(gv.w);
            c_state = f * c_state + ii * gg;
            h_last  = o * tanhfast(c_state);
            out[((size_t)t * BATCH + b0 + urow) * HID + h0 + ucol] = h_last;
        }
        if (write_tail && t == T_STEPS - 1) {
            size_t base = (size_t)T_STEPS * BATCH * HID;
            out[base + (size_t)(b0 + urow) * HID + h0 + ucol] = h_last;
            base += (size_t)BATCH * HID;
            out[base + (size_t)(b0 + urow) * HID + h0 + ucol] = c_state;
        }

        // ---- device-wide barrier (skip after last step) -------------------------
        if (t + 1 < T_STEPS) {
            __threadfence();
            __syncthreads();
            if (tid == 0) {
                atomicAdd(&g_bar, 1u);
                unsigned int target = (unsigned int)(t + 1) * NBLK;
                unsigned int v;
                do {
                    asm volatile("ld.acquire.gpu.u32 %0, [%1];" : "=r"(v) : "l"(&g_bar));
                } while (v < target);
            }
            __syncthreads();
        }
    }
}

// ---------------- launch ------------------------------------------------------
extern "C" void kernel_launch(void* const* d_in, const int* in_sizes, int n_in,
                              void* d_out, int out_size) {
    const float* x  = (const float*)d_in[0];
    const float* Wf = (const float*)d_in[1];
    const float* bf = (const float*)d_in[2];
    const float* Wi = (const float*)d_in[3];
    const float* bi = (const float*)d_in[4];
    const float* Wg = (const float*)d_in[5];
    const float* bg = (const float*)d_in[6];
    const float* Wo = (const float*)d_in[7];
    const float* bo = (const float*)d_in[8];
    float* out = (float*)d_out;

    const long long tbh = (long long)T_STEPS * BATCH * HID;
    int write_tail = ((long long)out_size >= tbh + 2LL * BATCH * HID) ? 1 : 0;

    cudaFuncSetAttribute(lstm_kernel, cudaFuncAttributeMaxDynamicSharedMemorySize,
                         SMEM2_BYTES);

    dim3 g1(T_STEPS * BATCH / 64, GATES / 64);
    gemm_x_kernel<<<g1, 256>>>(x, Wf, Wi, Wg, Wo, bf, bi, bg, bo);
    lstm_kernel<<<NBLK, 256, SMEM2_BYTES>>>(out, write_tail, Wf, Wi, Wg, Wo);
}

// round 4
// speedup vs baseline: 2.3739x; 1.5495x over previous
#include <cuda_runtime.h>
#include <cuda_fp16.h>
#include <cstdint>
#include <cstddef>

#define T_STEPS 512
#define BATCH   64
#define HID     512
#define GATES   2048   // 4*HID, interleaved j' = h*4 + gate (f,i,g,o)
#define DIN     512
#define NBLK    128    // 32 col-groups x 4 batch-groups

// ---------------- device scratch --------------------------------------------
__device__ float  g_Gx[67108864];          // 256 MB  Gx[(t*B+b)*2048 + j']
__device__ __half g_h16[2 * BATCH * HID];  // fp16 h double buffer
__device__ unsigned int g_bar;

// ---------------- helpers ----------------------------------------------------
__device__ __forceinline__ uint32_t smem_u32(const void* p) {
    uint32_t a;
    asm("{ .reg .u64 t; cvta.to.shared.u64 t, %1; cvt.u32.u64 %0, t; }"
        : "=r"(a) : "l"(p));
    return a;
}
__device__ __forceinline__ float sigf(float x) {
    return __fdividef(1.0f, 1.0f + __expf(-x));
}
__device__ __forceinline__ float tanhfast(float x) {
    return fmaf(2.0f, sigf(2.0f * x), -1.0f);
}
__device__ __forceinline__ unsigned long long pk2(float x, float y) {
    unsigned long long r;
    asm("mov.b64 %0, {%1, %2};" : "=l"(r) : "f"(x), "f"(y));
    return r;
}
__device__ __forceinline__ void fma2(unsigned long long& d, unsigned long long a,
                                     unsigned long long b) {
    asm("fma.rn.f32x2 %0, %1, %2, %0;" : "+l"(d) : "l"(a), "l"(b));
}
__device__ __forceinline__ void up2(unsigned long long v, float& x, float& y) {
    asm("mov.b64 {%0, %1}, %2;" : "=f"(x), "=f"(y) : "l"(v));
}
__device__ __forceinline__ void ldsm4(uint32_t& r0, uint32_t& r1, uint32_t& r2,
                                      uint32_t& r3, uint32_t addr) {
    asm volatile("ldmatrix.sync.aligned.m8n8.x4.shared.b16 {%0,%1,%2,%3}, [%4];"
                 : "=r"(r0), "=r"(r1), "=r"(r2), "=r"(r3) : "r"(addr));
}
__device__ __forceinline__ void hmma(float& c0, float& c1, float& c2, float& c3,
                                     uint32_t a0, uint32_t a1, uint32_t a2, uint32_t a3,
                                     uint32_t b0, uint32_t b1) {
    asm volatile("mma.sync.aligned.m16n8k16.row.col.f32.f16.f16.f32 "
                 "{%0,%1,%2,%3}, {%4,%5,%6,%7}, {%8,%9}, {%0,%1,%2,%3};"
                 : "+f"(c0), "+f"(c1), "+f"(c2), "+f"(c3)
                 : "r"(a0), "r"(a1), "r"(a2), "r"(a3), "r"(b0), "r"(b1));
}

// ---------------- input GEMM: Gx = X @ Wx^T + bias (fp32 f32x2) --------------
__global__ void __launch_bounds__(256) gemm_x_kernel(
    const float* __restrict__ X,
    const float* __restrict__ Wf, const float* __restrict__ Wi,
    const float* __restrict__ Wg, const float* __restrict__ Wo,
    const float* __restrict__ bf, const float* __restrict__ bi,
    const float* __restrict__ bg, const float* __restrict__ bo) {
    __shared__ __align__(16) float As[16][64];
    __shared__ __align__(16) float Bs[16][64];
    if (blockIdx.x == 0 && blockIdx.y == 0 && threadIdx.x == 0) g_bar = 0u;

    const int m0  = blockIdx.x * 64;
    const int n0  = blockIdx.y * 64;
    const int tid = threadIdx.x;
    const int tm4 = (tid >> 4) << 2;
    const int tn4 = (tid & 15) << 2;
    const int lr  = tid >> 2;
    const int lk  = (tid & 3) << 2;

    const float* Xp = X + (size_t)(m0 + lr) * DIN + lk;
    const int jp = n0 + lr;
    const int gg = jp & 3;
    const int hh = jp >> 2;
    const float* Wsel = (gg == 0) ? Wf : (gg == 1) ? Wi : (gg == 2) ? Wg : Wo;
    const float* Wp = Wsel + (size_t)hh * (DIN + HID) + lk;

    unsigned long long acc[4][2];
#pragma unroll
    for (int i = 0; i < 4; i++) { acc[i][0] = pk2(0.f, 0.f); acc[i][1] = pk2(0.f, 0.f); }

    for (int kt = 0; kt < DIN; kt += 16) {
        float4 av = *(const float4*)(Xp + kt);
        float4 bv = *(const float4*)(Wp + kt);
        __syncthreads();
        As[lk + 0][lr] = av.x; As[lk + 1][lr] = av.y;
        As[lk + 2][lr] = av.z; As[lk + 3][lr] = av.w;
        Bs[lk + 0][lr] = bv.x; Bs[lk + 1][lr] = bv.y;
        Bs[lk + 2][lr] = bv.z; Bs[lk + 3][lr] = bv.w;
        __syncthreads();
#pragma unroll
        for (int k = 0; k < 16; k++) {
            float4 a = *(const float4*)&As[k][tm4];
            ulonglong2 b2 = *(const ulonglong2*)&Bs[k][tn4];
            unsigned long long t0;
            t0 = pk2(a.x, a.x); fma2(acc[0][0], b2.x, t0); fma2(acc[0][1], b2.y, t0);
            t0 = pk2(a.y, a.y); fma2(acc[1][0], b2.x, t0); fma2(acc[1][1], b2.y, t0);
            t0 = pk2(a.z, a.z); fma2(acc[2][0], b2.x, t0); fma2(acc[2][1], b2.y, t0);
            t0 = pk2(a.w, a.w); fma2(acc[3][0], b2.x, t0); fma2(acc[3][1], b2.y, t0);
        }
    }
    const int hb = (n0 + tn4) >> 2;
    float4 bias = make_float4(bf[hb], bi[hb], bg[hb], bo[hb]);
#pragma unroll
    for (int i = 0; i < 4; i++) {
        float c0, c1, c2, c3;
        up2(acc[i][0], c0, c1);
        up2(acc[i][1], c2, c3);
        float4 o;
        o.x = c0 + bias.x; o.y = c1 + bias.y; o.z = c2 + bias.z; o.w = c3 + bias.w;
        *(float4*)(g_Gx + (size_t)(m0 + tm4 + i) * GATES + n0 + tn4) = o;
    }
}

// ---------------- persistent HMMA recurrent kernel ---------------------------
// 128 blocks: cb = bx&31 -> gate cols [64cb, 64cb+64) (h cells [16cb,16cb+16)),
//             nb = bx>>5 -> batch rows [16nb, 16nb+16).
// Wh held in registers as mma.m16n8k16 B fragments (64 regs/lane, loaded once).
// h(t-1) tile [16 x 512] fp16 in swizzled smem; A frags via ldmatrix.x4.
__global__ void __launch_bounds__(256, 1) lstm_kernel(
    float* __restrict__ out, int write_tail,
    const float* __restrict__ Wf, const float* __restrict__ Wi,
    const float* __restrict__ Wg, const float* __restrict__ Wo) {
    __shared__ __align__(1024) __half hA[16 * 512];   // 16KB, swizzled
    __shared__ __align__(16) float hsm[16 * 20];      // bounce tile [row][cell]

    const int tid  = threadIdx.x;
    const int w    = tid >> 5;
    const int lane = tid & 31;
    const int cb   = blockIdx.x & 31;
    const int nb   = blockIdx.x >> 5;
    const int c0g  = cb * 64;                // first gate col
    const int h0   = cb * 16;                // first h cell
    const int b0   = nb * 16;                // first batch row

    const int g8 = lane >> 2;                // row group 0..7
    const int tg = lane & 3;                 // thread-in-group

    // ---- prologue: build resident B fragments of Wh ---------------------------
    // warp w covers gate cols j = c0g + 8w + g8; lane holds B[k][n] pairs.
    uint32_t Bf[32][2];
    {
        const int jp = c0g + w * 8 + g8;
        const int gt = jp & 3;
        const int hh = jp >> 2;
        const float* Wsel = (gt == 0) ? Wf : (gt == 1) ? Wi : (gt == 2) ? Wg : Wo;
        const float* wr = Wsel + (size_t)hh * (DIN + HID) + DIN;
#pragma unroll
        for (int ks = 0; ks < 32; ks++) {
            float2 x = *(const float2*)(wr + ks * 16 + 2 * tg);
            float2 y = *(const float2*)(wr + ks * 16 + 2 * tg + 8);
            __half2 hx = __floats2half2_rn(x.x, x.y);
            __half2 hy = __floats2half2_rn(y.x, y.y);
            Bf[ks][0] = *(uint32_t*)&hx;
            Bf[ks][1] = *(uint32_t*)&hy;
        }
    }
    // zero h tile (t=0 uses zeros)
    for (int i = tid; i < 16 * 512 / 8; i += 256)
        *(uint4*)(hA + i * 8) = make_uint4(0u, 0u, 0u, 0u);
    __syncthreads();

    const uint32_t hA_base = smem_u32(hA);
    // ldmatrix lane address components: row = lane&15, chunk-half-sel = lane>>4
    const uint32_t lrow  = lane & 15;
    const uint32_t lrow7 = lrow & 7;
    const uint32_t lbase = hA_base + lrow * 1024;
    const uint32_t csel  = lane >> 4;

    // epilogue mapping: lane pair (tg even/odd) covers cell lc rows g8 / g8+8
    const int lc   = 2 * w + (tg >> 1);            // local cell 0..15
    const int myrow = g8 + ((tg & 1) ? 8 : 0);     // this lane's batch row
    const int j0   = c0g + w * 8 + (tg & 2) * 2;   // cell's first gate col
    float c_st = 0.f;

    for (int t = 0; t < T_STEPS; t++) {
        // ---- gather h(t-1) [16 x 512] fp16 into swizzled smem ------------------
        if (t > 0) {
            const __half* hsrc = g_h16 + (size_t)((t - 1) & 1) * BATCH * HID
                               + (size_t)b0 * HID;
#pragma unroll
            for (int i = 0; i < 4; i++) {
                int idx = tid + i * 256;             // 1024 chunks of 16B
                int r   = idx >> 6;
                int c   = idx & 63;
                uint4 v = __ldcg((const uint4*)(hsrc + (size_t)r * HID + c * 8));
                *(uint4*)((char*)hA + r * 1024 + ((c ^ (r & 7)) << 4)) = v;
            }
            __syncthreads();
        }

        // ---- prefetch Gx for this lane's row/cell ------------------------------
        float4 gx = __ldcg((const float4*)(
            g_Gx + ((size_t)t * BATCH + b0 + myrow) * GATES + j0));

        // ---- K-loop: 32 x m16n8k16, two interleaved accumulator chains ---------
        float e0 = 0.f, e1 = 0.f, e2 = 0.f, e3 = 0.f;
        float o0 = 0.f, o1 = 0.f, o2 = 0.f, o3 = 0.f;
#pragma unroll
        for (int ks = 0; ks < 32; ks++) {
            uint32_t c2 = 2 * ks + csel;
            uint32_t addr = lbase + (((c2 ^ lrow7)) << 4);
            uint32_t a0, a1, a2, a3;
            ldsm4(a0, a1, a2, a3, addr);
            if (ks & 1) hmma(o0, o1, o2, o3, a0, a1, a2, a3, Bf[ks][0], Bf[ks][1]);
            else        hmma(e0, e1, e2, e3, a0, a1, a2, a3, Bf[ks][0], Bf[ks][1]);
        }
        float c0 = e0 + o0, c1 = e1 + o1, c2v = e2 + o2, c3 = e3 + o3;

        // ---- exchange with xor-1 partner: even lane gets (g,o), odd gets (f,i) -
        float s0 = __shfl_xor_sync(0xffffffffu, c0, 1);
        float s1 = __shfl_xor_sync(0xffffffffu, c1, 1);
        float s2 = __shfl_xor_sync(0xffffffffu, c2v, 1);
        float s3 = __shfl_xor_sync(0xffffffffu, c3, 1);
        // even lane (tg even): row g8:   f=c0, i=c1, g=s0, o=s1
        // odd  lane (tg odd) : row g8+8: f=s2, i=s3, g=c2v, o=c3
        float pf, pi, pg, po;
        if (tg & 1) { pf = s2; pi = s3; pg = c2v; po = c3; }
        else        { pf = c0; pi = c1; pg = s0;  po = s1; }
        pf += gx.x; pi += gx.y; pg += gx.z; po += gx.w;

        float f  = sigf(pf);
        float ii = sigf(pi);
        float gv = tanhfast(pg);
        float oo = sigf(po);
        c_st = f * c_st + ii * gv;
        float hv = oo * tanhfast(c_st);
        hsm[myrow * 20 + lc] = hv;
        __syncthreads();

        // ---- writers: 64 threads, coalesced float4 + fp16 ----------------------
        if (tid < 64) {
            int row = tid >> 2;
            int c4  = (tid & 3) << 2;
            float4 v = *(const float4*)&hsm[row * 20 + c4];
            *(float4*)(out + ((size_t)t * BATCH + b0 + row) * HID + h0 + c4) = v;
            __half2 p01 = __floats2half2_rn(v.x, v.y);
            __half2 p23 = __floats2half2_rn(v.z, v.w);
            uint2 pk;
            pk.x = *(uint32_t*)&p01;
            pk.y = *(uint32_t*)&p23;
            *(uint2*)(g_h16 + (size_t)(t & 1) * BATCH * HID
                      + (size_t)(b0 + row) * HID + h0 + c4) = pk;
            if (write_tail && t == T_STEPS - 1) {
                *(float4*)(out + (size_t)T_STEPS * BATCH * HID
                           + (size_t)(b0 + row) * HID + h0 + c4) = v;
            }
        }

        if (t + 1 < T_STEPS) {
            // ---- device-wide barrier ------------------------------------------
            __threadfence();
            __syncthreads();
            if (tid == 0) {
                atomicAdd(&g_bar, 1u);
                unsigned int target = (unsigned int)(t + 1) * NBLK;
                unsigned int v;
                do {
                    asm volatile("ld.acquire.gpu.u32 %0, [%1];" : "=r"(v) : "l"(&g_bar));
                } while (v < target);
            }
            __syncthreads();
        }
    }

    // ---- tail: c state ---------------------------------------------------------
    if (write_tail) {
        __syncthreads();
        hsm[myrow * 20 + lc] = c_st;
        __syncthreads();
        if (tid < 64) {
            int row = tid >> 2;
            int c4  = (tid & 3) << 2;
            float4 v = *(const float4*)&hsm[row * 20 + c4];
            *(float4*)(out + (size_t)(T_STEPS + 1) * BATCH * HID
                       + (size_t)(b0 + row) * HID + h0 + c4) = v;
        }
    }
}

// ---------------- launch ------------------------------------------------------
extern "C" void kernel_launch(void* const* d_in, const int* in_sizes, int n_in,
                              void* d_out, int out_size) {
    const float* x  = (const float*)d_in[0];
    const float* Wf = (const float*)d_in[1];
    const float* bf = (const float*)d_in[2];
    const float* Wi = (const float*)d_in[3];
    const float* bi = (const float*)d_in[4];
    const float* Wg = (const float*)d_in[5];
    const float* bg = (const float*)d_in[6];
    const float* Wo = (const float*)d_in[7];
    const float* bo = (const float*)d_in[8];
    float* out = (float*)d_out;

    const long long tbh = (long long)T_STEPS * BATCH * HID;
    int write_tail = ((long long)out_size >= tbh + 2LL * BATCH * HID) ? 1 : 0;

    dim3 g1(T_STEPS * BATCH / 64, GATES / 64);
    gemm_x_kernel<<<g1, 256>>>(x, Wf, Wi, Wg, Wo, bf, bi, bg, bo);
    lstm_kernel<<<NBLK, 256>>>(out, write_tail, Wf, Wi, Wg, Wo);
}

// round 5
// speedup vs baseline: 3.9193x; 1.6510x over previous
#include <cuda_runtime.h>
#include <cuda_fp16.h>
#include <cstdint>
#include <cstddef>

#define T_STEPS 512
#define BATCH   64
#define HID     512
#define GATES   2048   // 4*HID, interleaved j' = h*4 + gate (f,i,g,o)
#define DIN     512
#define NBLK    128    // 32 col-groups x 4 batch-groups

// ---------------- device scratch --------------------------------------------
__device__ float  g_Gx[67108864];          // 256 MB  Gx[(t*B+b)*2048 + j'] (x@Wx^T, no bias)
__device__ __half g_h16[2 * BATCH * HID];  // fp16 h double buffer
__device__ unsigned int g_bar4[4 * 32];    // per batch-group barrier counters (128B apart)

// ---------------- helpers ----------------------------------------------------
__device__ __forceinline__ uint32_t smem_u32(const void* p) {
    uint32_t a;
    asm("{ .reg .u64 t; cvta.to.shared.u64 t, %1; cvt.u32.u64 %0, t; }"
        : "=r"(a) : "l"(p));
    return a;
}
__device__ __forceinline__ float sigf(float x) {
    return __fdividef(1.0f, 1.0f + __expf(-x));
}
__device__ __forceinline__ float tanhfast(float x) {
    return fmaf(2.0f, sigf(2.0f * x), -1.0f);
}
__device__ __forceinline__ void ldsm4(uint32_t& r0, uint32_t& r1, uint32_t& r2,
                                      uint32_t& r3, uint32_t addr) {
    asm volatile("ldmatrix.sync.aligned.m8n8.x4.shared.b16 {%0,%1,%2,%3}, [%4];"
                 : "=r"(r0), "=r"(r1), "=r"(r2), "=r"(r3) : "r"(addr));
}
__device__ __forceinline__ void hmma(float* c,
                                     uint32_t a0, uint32_t a1, uint32_t a2, uint32_t a3,
                                     uint32_t b0, uint32_t b1) {
    asm volatile("mma.sync.aligned.m16n8k16.row.col.f32.f16.f16.f32 "
                 "{%0,%1,%2,%3}, {%4,%5,%6,%7}, {%8,%9}, {%0,%1,%2,%3};"
                 : "+f"(c[0]), "+f"(c[1]), "+f"(c[2]), "+f"(c[3])
                 : "r"(a0), "r"(a1), "r"(a2), "r"(a3), "r"(b0), "r"(b1));
}

// ---------------- input GEMM (HMMA fp16): Gx = X @ Wx^T ----------------------
// M=32768, N=2048, K=512. Block 128x128, 256 thr (8 warps at 32x64), BK=32,
// double-buffered smem, 80B row stride (5*16B: odd -> conflict-free ldmatrix).
#define GX_SROW 40                       // halfs per smem row
#define GX_STG  (128 * GX_SROW * 2)      // stage stride bytes = 10240

__global__ void __launch_bounds__(256, 1) gemm_x_kernel(
    const float* __restrict__ X,
    const float* __restrict__ Wf, const float* __restrict__ Wi,
    const float* __restrict__ Wg, const float* __restrict__ Wo) {
    __shared__ __align__(16) __half sA[2][128 * GX_SROW];
    __shared__ __align__(16) __half sB[2][128 * GX_SROW];

    const int tid = threadIdx.x;
    if (blockIdx.x == 0 && blockIdx.y == 0 && tid < 4) g_bar4[tid * 32] = 0u;

    const int m0 = blockIdx.x * 128;
    const int n0 = blockIdx.y * 128;

    // loader mapping: rows = tid&127, k-half = (tid>>7)*16
    const int lrow = tid & 127;
    const int kh   = (tid >> 7) * 16;
    const float* xp = X + (size_t)(m0 + lrow) * DIN + kh;
    const int jp = n0 + lrow;
    const int gt = jp & 3;
    const int cell = jp >> 2;
    const float* Wsel = (gt == 0) ? Wf : (gt == 1) ? Wi : (gt == 2) ? Wg : Wo;
    const float* wp = Wsel + (size_t)cell * (DIN + HID) + kh;
    const uint32_t sts_off = (uint32_t)(lrow * 80 + kh * 2);

    const int w = tid >> 5, lane = tid & 31;
    const int wm = w >> 1, wn = w & 1;
    const uint32_t sAb = smem_u32(sA), sBb = smem_u32(sB);
    const uint32_t aAddr0 = sAb + (uint32_t)(wm * 32 + (lane & 15)) * 80 + (lane >> 4) * 16;
    const uint32_t bAddr0 = sBb + (uint32_t)(wn * 64 + (lane & 15)) * 80 + (lane >> 4) * 16;

    float acc[2][8][4];
#pragma unroll
    for (int i = 0; i < 2; i++)
#pragma unroll
        for (int j = 0; j < 8; j++)
#pragma unroll
            for (int q = 0; q < 4; q++) acc[i][j][q] = 0.f;

    uint32_t aR[8], bR[8];
#define GX_LOAD(c) do {                                                        \
    const float* xq = xp + (c) * 32;                                           \
    const float* wq = wp + (c) * 32;                                           \
    _Pragma("unroll")                                                          \
    for (int i = 0; i < 4; i++) {                                              \
        float4 v = *(const float4*)(xq + 4 * i);                               \
        __half2 h0 = __floats2half2_rn(v.x, v.y);                              \
        __half2 h1 = __floats2half2_rn(v.z, v.w);                              \
        aR[2 * i] = *(uint32_t*)&h0; aR[2 * i + 1] = *(uint32_t*)&h1;          \
        float4 u = *(const float4*)(wq + 4 * i);                               \
        __half2 g0 = __floats2half2_rn(u.x, u.y);                              \
        __half2 g1 = __floats2half2_rn(u.z, u.w);                              \
        bR[2 * i] = *(uint32_t*)&g0; bR[2 * i + 1] = *(uint32_t*)&g1;          \
    }                                                                          \
} while (0)
#define GX_STS(p) do {                                                         \
    *(uint4*)((char*)sA + (p) * GX_STG + sts_off) =                            \
        make_uint4(aR[0], aR[1], aR[2], aR[3]);                                \
    *(uint4*)((char*)sA + (p) * GX_STG + sts_off + 16) =                       \
        make_uint4(aR[4], aR[5], aR[6], aR[7]);                                \
    *(uint4*)((char*)sB + (p) * GX_STG + sts_off) =                            \
        make_uint4(bR[0], bR[1], bR[2], bR[3]);                                \
    *(uint4*)((char*)sB + (p) * GX_STG + sts_off + 16) =                       \
        make_uint4(bR[4], bR[5], bR[6], bR[7]);                                \
} while (0)

    GX_LOAD(0);
    GX_STS(0);

    for (int c = 0; c < 16; c++) {
        const uint32_t p = (uint32_t)(c & 1) * GX_STG;
        __syncthreads();
        if (c < 15) GX_LOAD(c + 1);
#pragma unroll
        for (int s = 0; s < 2; s++) {
            uint32_t A0[4], A1[4], B0[4], B1[4], B2[4], B3[4];
            ldsm4(A0[0], A0[1], A0[2], A0[3], aAddr0 + p + s * 32);
            ldsm4(A1[0], A1[1], A1[2], A1[3], aAddr0 + p + s * 32 + 16 * 80);
            ldsm4(B0[0], B0[1], B0[2], B0[3], bAddr0 + p + s * 32);
            ldsm4(B1[0], B1[1], B1[2], B1[3], bAddr0 + p + s * 32 + 16 * 80);
            ldsm4(B2[0], B2[1], B2[2], B2[3], bAddr0 + p + s * 32 + 32 * 80);
            ldsm4(B3[0], B3[1], B3[2], B3[3], bAddr0 + p + s * 32 + 48 * 80);
#pragma unroll
            for (int mt = 0; mt < 2; mt++) {
                uint32_t* A = mt ? A1 : A0;
                hmma(acc[mt][0], A[0], A[1], A[2], A[3], B0[0], B0[2]);
                hmma(acc[mt][1], A[0], A[1], A[2], A[3], B0[1], B0[3]);
                hmma(acc[mt][2], A[0], A[1], A[2], A[3], B1[0], B1[2]);
                hmma(acc[mt][3], A[0], A[1], A[2], A[3], B1[1], B1[3]);
                hmma(acc[mt][4], A[0], A[1], A[2], A[3], B2[0], B2[2]);
                hmma(acc[mt][5], A[0], A[1], A[2], A[3], B2[1], B2[3]);
                hmma(acc[mt][6], A[0], A[1], A[2], A[3], B3[0], B3[2]);
                hmma(acc[mt][7], A[0], A[1], A[2], A[3], B3[1], B3[3]);
            }
        }
        if (c < 15) GX_STS((c + 1) & 1);
    }

    // epilogue: lane (r = lane>>2, cols (lane&3)*2) float2 stores
#pragma unroll
    for (int mt = 0; mt < 2; mt++) {
        const int r = m0 + wm * 32 + mt * 16 + (lane >> 2);
#pragma unroll
        for (int nt = 0; nt < 8; nt++) {
            const int cc = n0 + wn * 64 + nt * 8 + (lane & 3) * 2;
            *(float2*)(g_Gx + (size_t)r * GATES + cc) =
                make_float2(acc[mt][nt][0], acc[mt][nt][1]);
            *(float2*)(g_Gx + (size_t)(r + 8) * GATES + cc) =
                make_float2(acc[mt][nt][2], acc[mt][nt][3]);
        }
    }
}

// ---------------- persistent HMMA recurrent kernel ---------------------------
// 128 blocks: cb = bx&31 -> gate cols [64cb,64cb+64), nb = bx>>5 -> batch rows
// [16nb,16nb+16). Wh resident in registers as B-frags; h tile in swizzled smem.
// Per-batch-group barrier (32 producers each). Bias added here (not in Gx).
__global__ void __launch_bounds__(256, 1) lstm_kernel(
    float* __restrict__ out, int write_tail,
    const float* __restrict__ Wf, const float* __restrict__ Wi,
    const float* __restrict__ Wg, const float* __restrict__ Wo,
    const float* __restrict__ bfp, const float* __restrict__ bip,
    const float* __restrict__ bgp, const float* __restrict__ bop) {
    __shared__ __align__(1024) __half hA[16 * 512];   // 16KB, swizzled
    __shared__ __align__(16) float hsm[16 * 20];      // bounce tile [row][cell]

    const int tid  = threadIdx.x;
    const int w    = tid >> 5;
    const int lane = tid & 31;
    const int cb   = blockIdx.x & 31;
    const int nb   = blockIdx.x >> 5;
    const int c0g  = cb * 64;                // first gate col
    const int h0   = cb * 16;                // first h cell
    const int b0   = nb * 16;                // first batch row
    unsigned int* barp = &g_bar4[nb * 32];

    const int g8 = lane >> 2;                // row group 0..7
    const int tg = lane & 3;                 // thread-in-group

    // ---- prologue: build resident B fragments of Wh ---------------------------
    uint32_t Bf[32][2];
    {
        const int jp = c0g + w * 8 + g8;
        const int gt = jp & 3;
        const int hh = jp >> 2;
        const float* Wsel = (gt == 0) ? Wf : (gt == 1) ? Wi : (gt == 2) ? Wg : Wo;
        const float* wr = Wsel + (size_t)hh * (DIN + HID) + DIN;
#pragma unroll
        for (int ks = 0; ks < 32; ks++) {
            float2 x = *(const float2*)(wr + ks * 16 + 2 * tg);
            float2 y = *(const float2*)(wr + ks * 16 + 2 * tg + 8);
            __half2 hx = __floats2half2_rn(x.x, x.y);
            __half2 hy = __floats2half2_rn(y.x, y.y);
            Bf[ks][0] = *(uint32_t*)&hx;
            Bf[ks][1] = *(uint32_t*)&hy;
        }
    }
    for (int i = tid; i < 16 * 512 / 8; i += 256)
        *(uint4*)(hA + i * 8) = make_uint4(0u, 0u, 0u, 0u);
    __syncthreads();

    const uint32_t hA_base = smem_u32(hA);
    const uint32_t lrow  = lane & 15;
    const uint32_t lrow7 = lrow & 7;
    const uint32_t lbase = hA_base + lrow * 1024;
    const uint32_t csel  = lane >> 4;

    // epilogue mapping
    const int lc    = 2 * w + (tg >> 1);           // local cell 0..15
    const int myrow = g8 + ((tg & 1) ? 8 : 0);     // this lane's batch row
    const int j0    = c0g + w * 8 + (tg & 2) * 2;  // cell's first gate col
    const int hcell = j0 >> 2;
    const float4 bb = make_float4(bfp[hcell], bip[hcell], bgp[hcell], bop[hcell]);
    float c_st = 0.f;

    // writer mapping (tid < 64)
    const int wrow = tid >> 2;
    const int wc4  = (tid & 3) << 2;

    // Gx prefetch for t=0
    float4 gx = __ldcg((const float4*)(
        g_Gx + ((size_t)0 * BATCH + b0 + myrow) * GATES + j0));

    for (int t = 0; t < T_STEPS; t++) {
        if (t > 0) {
            // ---- wait for producers of h(t-1), then gather ----------------------
            if (tid == 0) {
                unsigned int target = (unsigned int)t * 32u;
                unsigned int v;
                do {
                    asm volatile("ld.acquire.gpu.u32 %0, [%1];" : "=r"(v) : "l"(barp));
                } while (v < target);
            }
            __syncthreads();
            const __half* hsrc = g_h16 + (size_t)((t - 1) & 1) * BATCH * HID
                               + (size_t)b0 * HID;
#pragma unroll
            for (int i = 0; i < 4; i++) {
                int idx = tid + i * 256;
                int r   = idx >> 6;
                int c   = idx & 63;
                uint4 v = __ldcg((const uint4*)(hsrc + (size_t)r * HID + c * 8));
                *(uint4*)((char*)hA + r * 1024 + ((c ^ (r & 7)) << 4)) = v;
            }
            __syncthreads();
        }

        // ---- K-loop: 32 x m16n8k16, 4 interleaved accumulator chains -----------
        float q[4][4];
#pragma unroll
        for (int i = 0; i < 4; i++)
#pragma unroll
            for (int j = 0; j < 4; j++) q[i][j] = 0.f;
#pragma unroll
        for (int ks = 0; ks < 32; ks++) {
            uint32_t c2 = 2 * ks + csel;
            uint32_t addr = lbase + ((c2 ^ lrow7) << 4);
            uint32_t a0, a1, a2, a3;
            ldsm4(a0, a1, a2, a3, addr);
            hmma(q[ks & 3], a0, a1, a2, a3, Bf[ks][0], Bf[ks][1]);
        }
        float c0  = q[0][0] + q[1][0] + q[2][0] + q[3][0];
        float c1  = q[0][1] + q[1][1] + q[2][1] + q[3][1];
        float c2v = q[0][2] + q[1][2] + q[2][2] + q[3][2];
        float c3  = q[0][3] + q[1][3] + q[2][3] + q[3][3];

        // ---- xor-1 exchange: even lane handles row g8, odd row g8+8 ------------
        float s0 = __shfl_xor_sync(0xffffffffu, c0, 1);
        float s1 = __shfl_xor_sync(0xffffffffu, c1, 1);
        float s2 = __shfl_xor_sync(0xffffffffu, c2v, 1);
        float s3 = __shfl_xor_sync(0xffffffffu, c3, 1);
        float pf, pi, pg, po;
        if (tg & 1) { pf = s2; pi = s3; pg = c2v; po = c3; }
        else        { pf = c0; pi = c1; pg = s0;  po = s1; }
        pf += gx.x + bb.x;
        pi += gx.y + bb.y;
        pg += gx.z + bb.z;
        po += gx.w + bb.w;

        float f  = sigf(pf);
        float ii = sigf(pi);
        float gv = tanhfast(pg);
        float oo = sigf(po);
        c_st = f * c_st + ii * gv;
        float hv = oo * tanhfast(c_st);
        hsm[myrow * 20 + lc] = hv;
        __syncthreads();

        // ---- writers: fp16 h first (critical), then signal, then fp32 out ------
        float4 v;
        if (tid < 64) {
            v = *(const float4*)&hsm[wrow * 20 + wc4];
            __half2 p01 = __floats2half2_rn(v.x, v.y);
            __half2 p23 = __floats2half2_rn(v.z, v.w);
            uint2 pk;
            pk.x = *(uint32_t*)&p01;
            pk.y = *(uint32_t*)&p23;
            *(uint2*)(g_h16 + (size_t)(t & 1) * BATCH * HID
                      + (size_t)(b0 + wrow) * HID + h0 + wc4) = pk;
        }
        if (t + 1 < T_STEPS) {
            if (tid < 64) __threadfence();
            __syncthreads();
            if (tid == 0) atomicAdd(barp, 1u);
        }
        // off-critical-path work: fp32 out store + next Gx prefetch
        if (tid < 64) {
            *(float4*)(out + ((size_t)t * BATCH + b0 + wrow) * HID + h0 + wc4) = v;
            if (write_tail && t == T_STEPS - 1) {
                *(float4*)(out + (size_t)T_STEPS * BATCH * HID
                           + (size_t)(b0 + wrow) * HID + h0 + wc4) = v;
            }
        }
        if (t + 1 < T_STEPS) {
            gx = __ldcg((const float4*)(
                g_Gx + ((size_t)(t + 1) * BATCH + b0 + myrow) * GATES + j0));
        }
    }

    // ---- tail: c state ---------------------------------------------------------
    if (write_tail) {
        __syncthreads();
        hsm[myrow * 20 + lc] = c_st;
        __syncthreads();
        if (tid < 64) {
            float4 v = *(const float4*)&hsm[wrow * 20 + wc4];
            *(float4*)(out + (size_t)(T_STEPS + 1) * BATCH * HID
                       + (size_t)(b0 + wrow) * HID + h0 + wc4) = v;
        }
    }
}

// ---------------- launch ------------------------------------------------------
extern "C" void kernel_launch(void* const* d_in, const int* in_sizes, int n_in,
                              void* d_out, int out_size) {
    const float* x  = (const float*)d_in[0];
    const float* Wf = (const float*)d_in[1];
    const float* bf = (const float*)d_in[2];
    const float* Wi = (const float*)d_in[3];
    const float* bi = (const float*)d_in[4];
    const float* Wg = (const float*)d_in[5];
    const float* bg = (const float*)d_in[6];
    const float* Wo = (const float*)d_in[7];
    const float* bo = (const float*)d_in[8];
    float* out = (float*)d_out;

    const long long tbh = (long long)T_STEPS * BATCH * HID;
    int write_tail = ((long long)out_size >= tbh + 2LL * BATCH * HID) ? 1 : 0;

    dim3 g1(T_STEPS * BATCH / 128, GATES / 128);
    gemm_x_kernel<<<g1, 256>>>(x, Wf, Wi, Wg, Wo);
    lstm_kernel<<<NBLK, 256>>>(out, write_tail, Wf, Wi, Wg, Wo, bf, bi, bg, bo);
}

// round 6
// speedup vs baseline: 4.4144x; 1.1263x over previous
#include <cuda_runtime.h>
#include <cuda_fp16.h>
#include <cstdint>
#include <cstddef>

#define T_STEPS 512
#define BATCH   64
#define HID     512
#define GATES   2048   // 4*HID, interleaved j' = h*4 + gate (f,i,g,o)
#define DIN     512
#define NBLK    128    // 32 col-groups x 4 batch-groups

// ---------------- device scratch --------------------------------------------
__device__ __half g_h16[2 * BATCH * HID];  // fp16 h double buffer
__device__ unsigned int g_bar4[4 * 32];    // per batch-group barrier counters

// ---------------- helpers ----------------------------------------------------
__device__ __forceinline__ uint32_t smem_u32(const void* p) {
    uint32_t a;
    asm("{ .reg .u64 t; cvta.to.shared.u64 t, %1; cvt.u32.u64 %0, t; }"
        : "=r"(a) : "l"(p));
    return a;
}
__device__ __forceinline__ float sigf(float x) {
    return __fdividef(1.0f, 1.0f + __expf(-x));
}
__device__ __forceinline__ float tanhfast(float x) {
    return fmaf(2.0f, sigf(2.0f * x), -1.0f);
}
__device__ __forceinline__ void ldsm4(uint32_t& r0, uint32_t& r1, uint32_t& r2,
                                      uint32_t& r3, uint32_t addr) {
    asm volatile("ldmatrix.sync.aligned.m8n8.x4.shared.b16 {%0,%1,%2,%3}, [%4];"
                 : "=r"(r0), "=r"(r1), "=r"(r2), "=r"(r3) : "r"(addr));
}
__device__ __forceinline__ void hmma(float* c,
                                     uint32_t a0, uint32_t a1, uint32_t a2, uint32_t a3,
                                     uint32_t b0, uint32_t b1) {
    asm volatile("mma.sync.aligned.m16n8k16.row.col.f32.f16.f16.f32 "
                 "{%0,%1,%2,%3}, {%4,%5,%6,%7}, {%8,%9}, {%0,%1,%2,%3};"
                 : "+f"(c[0]), "+f"(c[1]), "+f"(c[2]), "+f"(c[3])
                 : "r"(a0), "r"(a1), "r"(a2), "r"(a3), "r"(b0), "r"(b1));
}

// dynamic smem layout (after 1KB alignment pad):
//   [0,      16KB)  hA  : h(t-1) tile  [16 rows][512 halfs], xor-swizzled
//   [16KB,   32KB)  xA  : x(t+1) tile  [16 rows][512 halfs], xor-swizzled
//   [32KB,   96KB)  WxF : Wx B-frags   [(w*32+ks)*32+lane] uint2
#define SMEM_BYTES (16384 + 16384 + 65536 + 1024)

// ---------------- fused persistent kernel ------------------------------------
// 128 blocks: cb = bx&31 -> gate cols [64cb,64cb+64), nb = bx>>5 -> batch rows
// [16nb,16nb+16). Wh resident in registers as B-frags. Per step:
//   wait -> gather h -> h-MMA (+GxReg from shadow) -> activations -> store h ->
//   signal -> [shadow] gather x(t+1), Gx-MMA -> GxReg(t+1).
__global__ void __launch_bounds__(256, 1) lstm_kernel(
    float* __restrict__ out, int write_tail, const float* __restrict__ X,
    const float* __restrict__ Wf, const float* __restrict__ Wi,
    const float* __restrict__ Wg, const float* __restrict__ Wo,
    const float* __restrict__ bfp, const float* __restrict__ bip,
    const float* __restrict__ bgp, const float* __restrict__ bop) {
    extern __shared__ char dynsm[];
    __shared__ __align__(16) float hsm[16 * 20];

    const uint32_t sb0 = smem_u32(dynsm);
    const uint32_t sb  = (sb0 + 1023u) & ~1023u;
    char* const basep = dynsm + (sb - sb0);
    char* const hAp   = basep;
    char* const xAp   = basep + 16384;
    char* const WxFp  = basep + 32768;
    const uint32_t hA_addr = sb;
    const uint32_t xA_addr = sb + 16384;

    const int tid  = threadIdx.x;
    const int w    = tid >> 5;
    const int lane = tid & 31;
    const int cb   = blockIdx.x & 31;
    const int nb   = blockIdx.x >> 5;
    const int c0g  = cb * 64;                // first gate col
    const int h0   = cb * 16;                // first h cell
    const int b0   = nb * 16;                // first batch row
    unsigned int* barp = &g_bar4[nb * 32];

    const int g8 = lane >> 2;                // row group 0..7
    const int tg = lane & 3;                 // thread-in-group

    // ---- prologue: Wh B-frags in regs; Wx B-frags in smem ---------------------
    uint32_t Bf[32][2];
    {
        const int jp = c0g + w * 8 + g8;
        const int gt = jp & 3;
        const int hh = jp >> 2;
        const float* Wsel = (gt == 0) ? Wf : (gt == 1) ? Wi : (gt == 2) ? Wg : Wo;
        const float* wh = Wsel + (size_t)hh * (DIN + HID) + DIN;   // h-part
        const float* wx = Wsel + (size_t)hh * (DIN + HID);         // x-part
        uint2* dst = (uint2*)WxFp;
#pragma unroll
        for (int ks = 0; ks < 32; ks++) {
            float2 x0 = *(const float2*)(wh + ks * 16 + 2 * tg);
            float2 y0 = *(const float2*)(wh + ks * 16 + 2 * tg + 8);
            __half2 hx = __floats2half2_rn(x0.x, x0.y);
            __half2 hy = __floats2half2_rn(y0.x, y0.y);
            Bf[ks][0] = *(uint32_t*)&hx;
            Bf[ks][1] = *(uint32_t*)&hy;
            float2 x1 = *(const float2*)(wx + ks * 16 + 2 * tg);
            float2 y1 = *(const float2*)(wx + ks * 16 + 2 * tg + 8);
            __half2 gx2 = __floats2half2_rn(x1.x, x1.y);
            __half2 gy2 = __floats2half2_rn(y1.x, y1.y);
            dst[(w * 32 + ks) * 32 + lane] =
                make_uint2(*(uint32_t*)&gx2, *(uint32_t*)&gy2);
        }
    }
    // zero hA (t=0 h-MMA reads zeros)
    for (int i = tid; i < 16 * 512 / 8; i += 256)
        *(uint4*)(hAp + i * 16) = make_uint4(0u, 0u, 0u, 0u);

    const uint32_t lrow  = lane & 15;
    const uint32_t lrow7 = lrow & 7;
    const uint32_t lbase = hA_addr + lrow * 1024;
    const uint32_t xbase = xA_addr + lrow * 1024;
    const uint32_t csel  = lane >> 4;

    // epilogue mapping
    const int lc    = 2 * w + (tg >> 1);           // local cell 0..15
    const int myrow = g8 + ((tg & 1) ? 8 : 0);     // this lane's batch row
    const int j0    = c0g + w * 8 + (tg & 2) * 2;  // cell's first gate col
    const int hcell = j0 >> 2;
    const float4 bb = make_float4(bfp[hcell], bip[hcell], bgp[hcell], bop[hcell]);
    float c_st = 0.f;

    // writer mapping (tid < 64)
    const int wrow = tid >> 2;
    const int wc4  = (tid & 3) << 2;

    // ---- x-tile gather + Gx-MMA helpers ---------------------------------------
    const uint2* wxf = (const uint2*)WxFp;
    float gxa0, gxa1, gxa2, gxa3;

#define GATHER_X(tt) do {                                                      \
    const float* xsrc = X + ((size_t)(tt) * BATCH + b0) * DIN;                 \
    _Pragma("unroll")                                                          \
    for (int i = 0; i < 4; i++) {                                              \
        int idx = tid + i * 256;                                               \
        int r   = idx >> 6;                                                    \
        int c   = idx & 63;                                                    \
        const float* p = xsrc + (size_t)r * DIN + c * 8;                       \
        float4 u  = __ldcg((const float4*)p);                                  \
        float4 v2 = __ldcg((const float4*)(p + 4));                            \
        __half2 a0 = __floats2half2_rn(u.x, u.y);                              \
        __half2 a1 = __floats2half2_rn(u.z, u.w);                              \
        __half2 a2 = __floats2half2_rn(v2.x, v2.y);                            \
        __half2 a3 = __floats2half2_rn(v2.z, v2.w);                            \
        *(uint4*)(xAp + r * 1024 + ((c ^ (r & 7)) << 4)) =                     \
            make_uint4(*(uint32_t*)&a0, *(uint32_t*)&a1,                       \
                       *(uint32_t*)&a2, *(uint32_t*)&a3);                      \
    }                                                                          \
} while (0)

#define GX_MMA() do {                                                         \
    float gq[4][4];                                                           \
    _Pragma("unroll")                                                         \
    for (int i = 0; i < 4; i++)                                               \
        _Pragma("unroll")                                                     \
        for (int j = 0; j < 4; j++) gq[i][j] = 0.f;                           \
    _Pragma("unroll")                                                         \
    for (int ks = 0; ks < 32; ks++) {                                         \
        uint32_t addr = xbase + ((((uint32_t)(2 * ks) + csel) ^ lrow7) << 4); \
        uint32_t a0, a1, a2, a3;                                              \
        ldsm4(a0, a1, a2, a3, addr);                                          \
        uint2 wv = wxf[(w * 32 + ks) * 32 + lane];                            \
        hmma(gq[ks & 3], a0, a1, a2, a3, wv.x, wv.y);                         \
    }                                                                         \
    gxa0 = gq[0][0] + gq[1][0] + gq[2][0] + gq[3][0];                         \
    gxa1 = gq[0][1] + gq[1][1] + gq[2][1] + gq[3][1];                         \
    gxa2 = gq[0][2] + gq[1][2] + gq[2][2] + gq[3][2];                         \
    gxa3 = gq[0][3] + gq[1][3] + gq[2][3] + gq[3][3];                         \
} while (0)

    // prologue Gx(0)
    GATHER_X(0);
    __syncthreads();
    GX_MMA();

    for (int t = 0; t < T_STEPS; t++) {
        if (t > 0) {
            // ---- wait for producers of h(t-1), then gather ----------------------
            if (tid == 0) {
                unsigned int target = (unsigned int)t * 32u;
                unsigned int v;
                do {
                    asm volatile("ld.acquire.gpu.u32 %0, [%1];" : "=r"(v) : "l"(barp));
                } while (v < target);
            }
            __syncthreads();
            const __half* hsrc = g_h16 + (size_t)((t - 1) & 1) * BATCH * HID
                               + (size_t)b0 * HID;
#pragma unroll
            for (int i = 0; i < 4; i++) {
                int idx = tid + i * 256;
                int r   = idx >> 6;
                int c   = idx & 63;
                uint4 v = __ldcg((const uint4*)(hsrc + (size_t)r * HID + c * 8));
                *(uint4*)(hAp + r * 1024 + ((c ^ (r & 7)) << 4)) = v;
            }
            __syncthreads();
        }

        // ---- h K-loop: 32 x m16n8k16, 4 interleaved chains ---------------------
        float q[4][4];
#pragma unroll
        for (int i = 0; i < 4; i++)
#pragma unroll
            for (int j = 0; j < 4; j++) q[i][j] = 0.f;
#pragma unroll
        for (int ks = 0; ks < 32; ks++) {
            uint32_t c2 = 2 * ks + csel;
            uint32_t addr = lbase + ((c2 ^ lrow7) << 4);
            uint32_t a0, a1, a2, a3;
            ldsm4(a0, a1, a2, a3, addr);
            hmma(q[ks & 3], a0, a1, a2, a3, Bf[ks][0], Bf[ks][1]);
        }
        // add Gx (same pre-shuffle fragment layout)
        float c0  = q[0][0] + q[1][0] + q[2][0] + q[3][0] + gxa0;
        float c1  = q[0][1] + q[1][1] + q[2][1] + q[3][1] + gxa1;
        float c2v = q[0][2] + q[1][2] + q[2][2] + q[3][2] + gxa2;
        float c3  = q[0][3] + q[1][3] + q[2][3] + q[3][3] + gxa3;

        // ---- xor-1 exchange: even lane handles row g8, odd row g8+8 ------------
        float s0 = __shfl_xor_sync(0xffffffffu, c0, 1);
        float s1 = __shfl_xor_sync(0xffffffffu, c1, 1);
        float s2 = __shfl_xor_sync(0xffffffffu, c2v, 1);
        float s3 = __shfl_xor_sync(0xffffffffu, c3, 1);
        float pf, pi, pg, po;
        if (tg & 1) { pf = s2; pi = s3; pg = c2v; po = c3; }
        else        { pf = c0; pi = c1; pg = s0;  po = s1; }
        pf += bb.x;
        pi += bb.y;
        pg += bb.z;
        po += bb.w;

        float f  = sigf(pf);
        float ii = sigf(pi);
        float gv = tanhfast(pg);
        float oo = sigf(po);
        c_st = f * c_st + ii * gv;
        float hv = oo * tanhfast(c_st);
        hsm[myrow * 20 + lc] = hv;
        __syncthreads();

        // ---- writers: fp16 h first (critical), then release-signal -------------
        float4 v;
        if (tid < 64) {
            v = *(const float4*)&hsm[wrow * 20 + wc4];
            __half2 p01 = __floats2half2_rn(v.x, v.y);
            __half2 p23 = __floats2half2_rn(v.z, v.w);
            uint2 pk;
            pk.x = *(uint32_t*)&p01;
            pk.y = *(uint32_t*)&p23;
            *(uint2*)(g_h16 + (size_t)(t & 1) * BATCH * HID
                      + (size_t)(b0 + wrow) * HID + h0 + wc4) = pk;
        }
        if (t + 1 < T_STEPS) {
            __syncthreads();
            if (tid == 0)
                asm volatile("red.release.gpu.global.add.u32 [%0], %1;"
                             :: "l"(barp), "r"(1u) : "memory");
        }
        // off-critical-path: fp32 out store
        if (tid < 64) {
            *(float4*)(out + ((size_t)t * BATCH + b0 + wrow) * HID + h0 + wc4) = v;
            if (write_tail && t == T_STEPS - 1) {
                *(float4*)(out + (size_t)T_STEPS * BATCH * HID
                           + (size_t)(b0 + wrow) * HID + h0 + wc4) = v;
            }
        }

        // ---- shadow: compute Gx(t+1) while other blocks catch up ---------------
        if (t + 1 < T_STEPS) {
            GATHER_X(t + 1);
            __syncthreads();
            GX_MMA();
        }
    }

    // ---- tail: c state ---------------------------------------------------------
    if (write_tail) {
        __syncthreads();
        hsm[myrow * 20 + lc] = c_st;
        __syncthreads();
        if (tid < 64) {
            float4 v = *(const float4*)&hsm[wrow * 20 + wc4];
            *(float4*)(out + (size_t)(T_STEPS + 1) * BATCH * HID
                       + (size_t)(b0 + wrow) * HID + h0 + wc4) = v;
        }
    }
}

// ---------------- launch ------------------------------------------------------
extern "C" void kernel_launch(void* const* d_in, const int* in_sizes, int n_in,
                              void* d_out, int out_size) {
    const float* x  = (const float*)d_in[0];
    const float* Wf = (const float*)d_in[1];
    const float* bf = (const float*)d_in[2];
    const float* Wi = (const float*)d_in[3];
    const float* bi = (const float*)d_in[4];
    const float* Wg = (const float*)d_in[5];
    const float* bg = (const float*)d_in[6];
    const float* Wo = (const float*)d_in[7];
    const float* bo = (const float*)d_in[8];
    float* out = (float*)d_out;

    const long long tbh = (long long)T_STEPS * BATCH * HID;
    int write_tail = ((long long)out_size >= tbh + 2LL * BATCH * HID) ? 1 : 0;

    void* barp = nullptr;
    cudaGetSymbolAddress(&barp, g_bar4);
    cudaMemsetAsync(barp, 0, sizeof(unsigned int) * 4 * 32, 0);

    cudaFuncSetAttribute(lstm_kernel, cudaFuncAttributeMaxDynamicSharedMemorySize,
                         SMEM_BYTES);
    lstm_kernel<<<NBLK, 256, SMEM_BYTES>>>(out, write_tail, x,
                                           Wf, Wi, Wg, Wo, bf, bi, bg, bo);
}

// round 7
// speedup vs baseline: 5.6104x; 1.2709x over previous
#include <cuda_runtime.h>
#include <cuda_fp16.h>
#include <cstdint>
#include <cstddef>

#define T_STEPS 512
#define BATCH   64
#define HID     512
#define GATES   2048   // 4*HID, interleaved j' = h*4 + gate (f,i,g,o)
#define DIN     512
#define NBLK    128    // 32 col-groups x 4 batch-groups

// ---------------- device scratch --------------------------------------------
__device__ __half g_h16[2 * BATCH * HID];  // fp16 h double buffer
__device__ unsigned int g_bar4[4 * 32];    // per batch-group barrier counters

// ---------------- helpers ----------------------------------------------------
__device__ __forceinline__ uint32_t smem_u32(const void* p) {
    uint32_t a;
    asm("{ .reg .u64 t; cvta.to.shared.u64 t, %1; cvt.u32.u64 %0, t; }"
        : "=r"(a) : "l"(p));
    return a;
}
__device__ __forceinline__ float sigf(float x) {
    return __fdividef(1.0f, 1.0f + __expf(-x));
}
__device__ __forceinline__ float tanhfast(float x) {
    return fmaf(2.0f, sigf(2.0f * x), -1.0f);
}
__device__ __forceinline__ void ldsm4(uint32_t& r0, uint32_t& r1, uint32_t& r2,
                                      uint32_t& r3, uint32_t addr) {
    asm volatile("ldmatrix.sync.aligned.m8n8.x4.shared.b16 {%0,%1,%2,%3}, [%4];"
                 : "=r"(r0), "=r"(r1), "=r"(r2), "=r"(r3) : "r"(addr));
}
__device__ __forceinline__ void hmma(float* c,
                                     uint32_t a0, uint32_t a1, uint32_t a2, uint32_t a3,
                                     uint32_t b0, uint32_t b1) {
    asm volatile("mma.sync.aligned.m16n8k16.row.col.f32.f16.f16.f32 "
                 "{%0,%1,%2,%3}, {%4,%5,%6,%7}, {%8,%9}, {%0,%1,%2,%3};"
                 : "+f"(c[0]), "+f"(c[1]), "+f"(c[2]), "+f"(c[3])
                 : "r"(a0), "r"(a1), "r"(a2), "r"(a3), "r"(b0), "r"(b1));
}
__device__ __forceinline__ uint32_t pkh2(float x, float y) {
    __half2 h = __floats2half2_rn(x, y);
    return *(uint32_t*)&h;
}

// dynamic smem layout (after 1KB alignment pad):
//   [0,    16K)  hA   : h(t-1) tile [16 r][512 halfs], xor-swizzled
//   [16K,  32K)  xA0  : x tile buffer 0
//   [32K,  48K)  xA1  : x tile buffer 1
//   [48K, 112K)  WxF  : Wx B-frags  uint4[(w*16+ks)*32 + lane]
//   [112K,120K)  exh/exx : k-half exchange buffers (float4 x 256 each)
#define SMEM_BYTES (120 * 1024 + 1024)

// ---------------- fused persistent kernel ------------------------------------
// 128 blocks: cb=bx&31 -> gate cols [64cb,64cb+64), nb=bx>>5 -> batch rows
// [16nb,16nb+16). Warp w = (colpair u=w>>1, k-half kv=w&1): 16 cols, 256 K.
// Per step: spin -> gather h -> fused MMA (h(t) + Gx(t+1)) -> k-half exchange
// -> activations -> store h -> signal -> gather x(t+2) (shadow, issue only).
__global__ void __launch_bounds__(256, 1) lstm_kernel(
    float* __restrict__ out, int write_tail, const float* __restrict__ X,
    const float* __restrict__ Wf, const float* __restrict__ Wi,
    const float* __restrict__ Wg, const float* __restrict__ Wo,
    const float* __restrict__ bfp, const float* __restrict__ bip,
    const float* __restrict__ bgp, const float* __restrict__ bop) {
    extern __shared__ char dynsm[];
    __shared__ __align__(16) float hsm[16 * 20];

    const uint32_t sb0 = smem_u32(dynsm);
    const uint32_t sb  = (sb0 + 1023u) & ~1023u;
    char* const basep = dynsm + (sb - sb0);
    char* const hAp   = basep;
    char* const xA0p  = basep + 16 * 1024;
    char* const xA1p  = basep + 32 * 1024;
    uint4* const wxf4 = (uint4*)(basep + 48 * 1024);
    float4* const exh = (float4*)(basep + 112 * 1024);
    float4* const exx = exh + 256;
    const uint32_t hA_addr  = sb;
    const uint32_t xA0_addr = sb + 16 * 1024;
    const uint32_t xA1_addr = sb + 32 * 1024;

    const int tid  = threadIdx.x;
    const int w    = tid >> 5;
    const int lane = tid & 31;
    const int cb   = blockIdx.x & 31;
    const int nb   = blockIdx.x >> 5;
    const int c0g  = cb * 64;
    const int h0   = cb * 16;
    const int b0   = nb * 16;
    unsigned int* barp = &g_bar4[nb * 32];

    const int g8 = lane >> 2;
    const int tg = lane & 3;
    const int u  = w >> 1;               // col-pair group (16 cols)
    const int kv = w & 1;                // k-half

    // ---- prologue: Wh B-frags (regs) + Wx B-frags (smem) ----------------------
    uint32_t Bf[16][2][2];
    {
        const int j0c = c0g + 16 * u + g8;       // nt0 col; nt1 = j0c + 8
        const int gt  = j0c & 3;
        const int hh0 = j0c >> 2;
        const float* Wsel = (gt == 0) ? Wf : (gt == 1) ? Wi : (gt == 2) ? Wg : Wo;
        const float* w0 = Wsel + (size_t)hh0 * (DIN + HID);
        const float* w1 = Wsel + (size_t)(hh0 + 2) * (DIN + HID);
#pragma unroll
        for (int ks = 0; ks < 16; ks++) {
            const int k0 = (kv * 16 + ks) * 16 + 2 * tg;
            {   // h-part frags
                float2 a0 = *(const float2*)(w0 + DIN + k0);
                float2 b0v = *(const float2*)(w0 + DIN + k0 + 8);
                Bf[ks][0][0] = pkh2(a0.x, a0.y);
                Bf[ks][0][1] = pkh2(b0v.x, b0v.y);
                float2 a1 = *(const float2*)(w1 + DIN + k0);
                float2 b1v = *(const float2*)(w1 + DIN + k0 + 8);
                Bf[ks][1][0] = pkh2(a1.x, a1.y);
                Bf[ks][1][1] = pkh2(b1v.x, b1v.y);
            }
            {   // x-part frags -> smem
                float2 a0 = *(const float2*)(w0 + k0);
                float2 b0v = *(const float2*)(w0 + k0 + 8);
                float2 a1 = *(const float2*)(w1 + k0);
                float2 b1v = *(const float2*)(w1 + k0 + 8);
                wxf4[(w * 16 + ks) * 32 + lane] =
                    make_uint4(pkh2(a0.x, a0.y), pkh2(b0v.x, b0v.y),
                               pkh2(a1.x, a1.y), pkh2(b1v.x, b1v.y));
            }
        }
    }
    for (int i = tid; i < 1024; i += 256)
        *(uint4*)(hAp + i * 16) = make_uint4(0u, 0u, 0u, 0u);

    const uint32_t lrow  = lane & 15;
    const uint32_t lrow7 = lrow & 7;
    const uint32_t lbase  = hA_addr + lrow * 1024;
    const uint32_t x0base = xA0_addr + lrow * 1024;
    const uint32_t x1base = xA1_addr + lrow * 1024;
    const uint32_t csel  = lane >> 4;
    const uint32_t kofs  = (uint32_t)(kv * 16);   // this warp's kstep offset

    // epilogue mapping (owned cols after exchange = c0g + 8w .. +8, unchanged)
    const int lc    = 2 * w + (tg >> 1);
    const int myrow = g8 + ((tg & 1) ? 8 : 0);
    const int j0    = c0g + 8 * w + (tg & 2) * 2;
    const int hcell = j0 >> 2;
    const float4 bb = make_float4(bfp[hcell], bip[hcell], bgp[hcell], bop[hcell]);
    float c_st = 0.f;
    const int wrow = tid >> 2;
    const int wc4  = (tid & 3) << 2;

#define GATHER_X(tt, dstp) do {                                                \
    const float* xsrc = X + ((size_t)(tt) * BATCH + b0) * DIN;                 \
    _Pragma("unroll")                                                          \
    for (int i_ = 0; i_ < 4; i_++) {                                           \
        int idx_ = tid + i_ * 256;                                             \
        int r_   = idx_ >> 6;                                                  \
        int c_   = idx_ & 63;                                                  \
        const float* p_ = xsrc + (size_t)r_ * DIN + c_ * 8;                    \
        float4 u_ = __ldcg((const float4*)p_);                                 \
        float4 v_ = __ldcg((const float4*)(p_ + 4));                           \
        *(uint4*)((dstp) + r_ * 1024 + ((c_ ^ (r_ & 7)) << 4)) =               \
            make_uint4(pkh2(u_.x, u_.y), pkh2(u_.z, u_.w),                     \
                       pkh2(v_.x, v_.y), pkh2(v_.z, v_.w));                    \
    }                                                                          \
} while (0)

    // ---- prologue: Gx(0) from buf0, then gather x(1) into buf1 ----------------
    float gxa0, gxa1, gxa2, gxa3;
    GATHER_X(0, xA0p);
    __syncthreads();
    {
        float qx0[4] = {0.f, 0.f, 0.f, 0.f}, qx1[4] = {0.f, 0.f, 0.f, 0.f};
#pragma unroll
        for (int ks = 0; ks < 16; ks++) {
            uint32_t kk = 2 * (kofs + ks) + csel;
            uint32_t a0, a1, a2, a3;
            ldsm4(a0, a1, a2, a3, x0base + ((kk ^ lrow7) << 4));
            uint4 wv = wxf4[(w * 16 + ks) * 32 + lane];
            hmma(qx0, a0, a1, a2, a3, wv.x, wv.y);
            hmma(qx1, a0, a1, a2, a3, wv.z, wv.w);
        }
        float* give = kv ? qx0 : qx1;
        exx[w * 32 + lane] = make_float4(give[0], give[1], give[2], give[3]);
        __syncthreads();
        float4 px = exx[(w ^ 1) * 32 + lane];
        float* keep = kv ? qx1 : qx0;
        gxa0 = keep[0] + px.x;
        gxa1 = keep[1] + px.y;
        gxa2 = keep[2] + px.z;
        gxa3 = keep[3] + px.w;
    }
    GATHER_X(1, xA1p);

    for (int t = 0; t < T_STEPS; t++) {
        if (t > 0) {
            // ---- all-thread spin for producers of h(t-1) ------------------------
            unsigned int target = (unsigned int)t * 32u;
            unsigned int v;
            do {
                asm volatile("ld.acquire.gpu.u32 %0, [%1];" : "=r"(v) : "l"(barp));
            } while (v < target);
            const __half* hsrc = g_h16 + (size_t)((t - 1) & 1) * BATCH * HID
                               + (size_t)b0 * HID;
#pragma unroll
            for (int i = 0; i < 4; i++) {
                int idx = tid + i * 256;
                int r   = idx >> 6;
                int c   = idx & 63;
                uint4 vv = __ldcg((const uint4*)(hsrc + (size_t)r * HID + c * 8));
                *(uint4*)(hAp + r * 1024 + ((c ^ (r & 7)) << 4)) = vv;
            }
        }
        __syncthreads();

        // ---- fused K-half loop: h(t)-MMA + Gx(t+1)-MMA -------------------------
        const uint32_t xbase = ((t + 1) & 1) ? x1base : x0base;
        float qh0[4] = {0.f, 0.f, 0.f, 0.f}, qh1[4] = {0.f, 0.f, 0.f, 0.f};
        float qx0[4] = {0.f, 0.f, 0.f, 0.f}, qx1[4] = {0.f, 0.f, 0.f, 0.f};
#pragma unroll
        for (int ks = 0; ks < 16; ks++) {
            uint32_t kk = (2 * (kofs + ks) + csel) ^ lrow7;
            uint32_t a0, a1, a2, a3;
            ldsm4(a0, a1, a2, a3, lbase + (kk << 4));
            hmma(qh0, a0, a1, a2, a3, Bf[ks][0][0], Bf[ks][0][1]);
            hmma(qh1, a0, a1, a2, a3, Bf[ks][1][0], Bf[ks][1][1]);
            uint32_t b0r, b1r, b2r, b3r;
            ldsm4(b0r, b1r, b2r, b3r, xbase + (kk << 4));
            uint4 wv = wxf4[(w * 16 + ks) * 32 + lane];
            hmma(qx0, b0r, b1r, b2r, b3r, wv.x, wv.y);
            hmma(qx1, b0r, b1r, b2r, b3r, wv.z, wv.w);
        }

        // ---- k-half exchange (give away tile 1-kv, keep tile kv) ---------------
        {
            float* gh = kv ? qh0 : qh1;
            float* gx = kv ? qx0 : qx1;
            exh[w * 32 + lane] = make_float4(gh[0], gh[1], gh[2], gh[3]);
            exx[w * 32 + lane] = make_float4(gx[0], gx[1], gx[2], gx[3]);
        }
        __syncthreads();
        float c0, c1, c2v, c3;
        {
            float4 ph = exh[(w ^ 1) * 32 + lane];
            float4 px = exx[(w ^ 1) * 32 + lane];
            float* kh = kv ? qh1 : qh0;
            float* kx = kv ? qx1 : qx0;
            c0  = kh[0] + ph.x + gxa0;
            c1  = kh[1] + ph.y + gxa1;
            c2v = kh[2] + ph.z + gxa2;
            c3  = kh[3] + ph.w + gxa3;
            gxa0 = kx[0] + px.x;             // Gx(t+1) for next iteration
            gxa1 = kx[1] + px.y;
            gxa2 = kx[2] + px.z;
            gxa3 = kx[3] + px.w;
        }

        // ---- xor-1 exchange + activations --------------------------------------
        float s0 = __shfl_xor_sync(0xffffffffu, c0, 1);
        float s1 = __shfl_xor_sync(0xffffffffu, c1, 1);
        float s2 = __shfl_xor_sync(0xffffffffu, c2v, 1);
        float s3 = __shfl_xor_sync(0xffffffffu, c3, 1);
        float pf, pi, pg, po;
        if (tg & 1) { pf = s2; pi = s3; pg = c2v; po = c3; }
        else        { pf = c0; pi = c1; pg = s0;  po = s1; }
        pf += bb.x;
        pi += bb.y;
        pg += bb.z;
        po += bb.w;

        float f  = sigf(pf);
        float ii = sigf(pi);
        float gv = tanhfast(pg);
        float oo = sigf(po);
        c_st = f * c_st + ii * gv;
        float hv = oo * tanhfast(c_st);
        hsm[myrow * 20 + lc] = hv;
        __syncthreads();

        // ---- writers: fp16 h (critical) -> signal -> fp32 out ------------------
        float4 v4;
        if (tid < 64) {
            v4 = *(const float4*)&hsm[wrow * 20 + wc4];
            uint2 pk;
            pk.x = pkh2(v4.x, v4.y);
            pk.y = pkh2(v4.z, v4.w);
            *(uint2*)(g_h16 + (size_t)(t & 1) * BATCH * HID
                      + (size_t)(b0 + wrow) * HID + h0 + wc4) = pk;
        }
        if (t + 1 < T_STEPS) {
            __syncthreads();
            if (tid == 0)
                asm volatile("red.release.gpu.global.add.u32 [%0], %1;"
                             :: "l"(barp), "r"(1u) : "memory");
        }
        if (tid < 64) {
            *(float4*)(out + ((size_t)t * BATCH + b0 + wrow) * HID + h0 + wc4) = v4;
            if (write_tail && t == T_STEPS - 1) {
                *(float4*)(out + (size_t)T_STEPS * BATCH * HID
                           + (size_t)(b0 + wrow) * HID + h0 + wc4) = v4;
            }
        }

        // ---- shadow: gather x(t+2) (LDG issue only) ----------------------------
        if (t + 2 < T_STEPS) {
            char* xdst = (t & 1) ? xA1p : xA0p;
            GATHER_X(t + 2, xdst);
        }
    }

    // ---- tail: c state ---------------------------------------------------------
    if (write_tail) {
        __syncthreads();
        hsm[myrow * 20 + lc] = c_st;
        __syncthreads();
        if (tid < 64) {
            float4 v4 = *(const float4*)&hsm[wrow * 20 + wc4];
            *(float4*)(out + (size_t)(T_STEPS + 1) * BATCH * HID
                       + (size_t)(b0 + wrow) * HID + h0 + wc4) = v4;
        }
    }
}

// ---------------- launch ------------------------------------------------------
extern "C" void kernel_launch(void* const* d_in, const int* in_sizes, int n_in,
                              void* d_out, int out_size) {
    const float* x  = (const float*)d_in[0];
    const float* Wf = (const float*)d_in[1];
    const float* bf = (const float*)d_in[2];
    const float* Wi = (const float*)d_in[3];
    const float* bi = (const float*)d_in[4];
    const float* Wg = (const float*)d_in[5];
    const float* bg = (const float*)d_in[6];
    const float* Wo = (const float*)d_in[7];
    const float* bo = (const float*)d_in[8];
    float* out = (float*)d_out;

    const long long tbh = (long long)T_STEPS * BATCH * HID;
    int write_tail = ((long long)out_size >= tbh + 2LL * BATCH * HID) ? 1 : 0;

    void* barp = nullptr;
    cudaGetSymbolAddress(&barp, g_bar4);
    cudaMemsetAsync(barp, 0, sizeof(unsigned int) * 4 * 32, 0);

    cudaFuncSetAttribute(lstm_kernel, cudaFuncAttributeMaxDynamicSharedMemorySize,
                         SMEM_BYTES);
    lstm_kernel<<<NBLK, 256, SMEM_BYTES>>>(out, write_tail, x,
                                           Wf, Wi, Wg, Wo, bf, bi, bg, bo);
}